// round 9
// baseline (speedup 1.0000x reference)
#include <cuda_runtime.h>
#include <cuda_bf16.h>
#include <cstdint>

// SR-GNN forward. Shapes fixed: B=1024, N=50, S=50, H=128, V=100000
#define Bb 1024
#define Nn 50
#define Ss 50
#define Hh 128
#define Vv 100000
#define V1 (Vv - 1)

// ---------------- scratch ---------------------------------------------------
__device__ float g_h     [Bb * Nn * Hh];
__device__ float g_cat   [Bb * Nn * 640];     // [hin(128) | hout(128) | gh(384)]
__device__ float g_inputs[Bb * Nn * 2 * Hh];
__device__ float g_gi    [Bb * Nn * 3 * Hh];
__device__ float g_newh  [Bb * Nn * Hh];
__device__ float g_seqh  [Bb * Ss * Hh];
__device__ float g_ht    [Bb * Hh];
__device__ float g_q1    [Bb * Hh];
__device__ float g_q2    [Bb * Ss * Hh];
__device__ float g_avec  [Bb * Hh];
__device__ float g_wr    [212992];            // packed tf32-rounded weights
__device__ float g_bcat  [640];               // packed bias for cat GEMM

// packed weight offsets (floats)
#define WR_CAT 0                  // 640x128 = 81920
#define WR_WIH 81920              // 384x256 = 98304
#define WR_FC1 180224             // 128x128 = 16384
#define WR_FC2 196608             // 128x128 = 16384

// ---------------- tf32 helpers ----------------------------------------------
__device__ __forceinline__ uint32_t f2tf32(float x) {
    uint32_t r;
    asm("cvt.rna.tf32.f32 %0, %1;" : "=r"(r) : "f"(x));
    return r;
}
__device__ __forceinline__ float roundtf(float x) {
    return __uint_as_float(f2tf32(x));
}
__device__ __forceinline__ void mma_tf32(float* c, const uint32_t* a,
                                         const uint32_t* b) {
    asm volatile(
        "mma.sync.aligned.m16n8k8.row.col.f32.tf32.tf32.f32 "
        "{%0,%1,%2,%3}, {%4,%5,%6,%7}, {%8,%9}, {%0,%1,%2,%3};"
        : "+f"(c[0]), "+f"(c[1]), "+f"(c[2]), "+f"(c[3])
        : "r"(a[0]), "r"(a[1]), "r"(a[2]), "r"(a[3]), "r"(b[0]), "r"(b[1]));
}
__device__ __forceinline__ void cp16(uint32_t dst, const void* src, bool pred) {
    int sz = pred ? 16 : 0;
    asm volatile("cp.async.cg.shared.global [%0], [%1], 16, %2;\n"
                 :: "r"(dst), "l"(src), "r"(sz));
}

// ---------------- prep kernels ----------------------------------------------
__global__ void round_kernel(const float* __restrict__ src,
                             float* __restrict__ dst, int n4) {
    int i = blockIdx.x * blockDim.x + threadIdx.x;
    if (i >= n4) return;
    float4 v = ((const float4*)src)[i];
    ((float4*)dst)[i] = make_float4(roundtf(v.x), roundtf(v.y),
                                    roundtf(v.z), roundtf(v.w));
}

// pack [ein_w; eou_w; w_hh] rows (640x128) rounded + bias
__global__ void pack_cat_kernel(const float* __restrict__ ein_w,
                                const float* __restrict__ eou_w,
                                const float* __restrict__ w_hh,
                                const float* __restrict__ ein_b,
                                const float* __restrict__ eou_b,
                                const float* __restrict__ b_hh,
                                float* __restrict__ wcat,
                                float* __restrict__ bcat) {
    int i = blockIdx.x * blockDim.x + threadIdx.x;   // 640*32 float4s
    if (i < 640 * 32) {
        int r = i >> 5, q = i & 31;
        const float* src = (r < 128) ? (ein_w + (size_t)r * Hh)
                         : (r < 256) ? (eou_w + (size_t)(r - 128) * Hh)
                                     : (w_hh + (size_t)(r - 256) * Hh);
        float4 v = ((const float4*)src)[q];
        ((float4*)wcat)[i] = make_float4(roundtf(v.x), roundtf(v.y),
                                         roundtf(v.z), roundtf(v.w));
    }
    if (i < 640) {
        bcat[i] = (i < 128) ? ein_b[i]
                : (i < 256) ? eou_b[i - 128]
                            : b_hh[i - 256];
    }
}

// ---------------- HMMA tf32 GEMM (generic) ----------------------------------
// C[M,N] = A[M,K] @ W[N,K]^T (+bias). Inputs pre-rounded to tf32.
// CTA 128x128, 128 threads = 4 warps (2x2 of 64x64), BK=32, double-buffered.
#define GBUF 18432
__global__ void __launch_bounds__(128, 2)
gemm2_kernel(const float* __restrict__ A, const float* __restrict__ W,
             const float* __restrict__ bias, float* __restrict__ C,
             int M, int N, int K) {
    extern __shared__ char dsm[];
    const uint32_t sbase = (uint32_t)__cvta_generic_to_shared(dsm);
    const int tid  = threadIdx.x;
    const int warp = tid >> 5, lane = tid & 31;
    const int g  = lane >> 2;
    const int tg = lane & 3;
    const int wm = (warp & 1) * 64;
    const int wn = (warp >> 1) * 64;
    const int m0 = blockIdx.y * 128;
    const int n0 = blockIdx.x * 128;

    float acc[4][8][4];
#pragma unroll
    for (int mt = 0; mt < 4; mt++)
#pragma unroll
        for (int nt = 0; nt < 8; nt++)
#pragma unroll
            for (int i = 0; i < 4; i++) acc[mt][nt][i] = 0.f;

    const int nch = K >> 5;

    auto stage = [&](int c, int s) {
        const int kt = c * 32;
        uint32_t aB = sbase + s * GBUF;
        uint32_t bB = sbase + 2 * GBUF + s * GBUF;
#pragma unroll
        for (int i = 0; i < 4; i++) {
            int idx = tid + i * 128;
#pragma unroll
            for (int h = 0; h < 2; h++) {
                int id2 = idx + h * 512;
                int row = id2 >> 3, q = id2 & 7;
                bool pa = (m0 + row) < M;
                const float* sa = pa ? (A + (size_t)(m0 + row) * K + kt + q * 4) : A;
                cp16(aB + row * 144 + q * 16, sa, pa);
                bool pb = (n0 + row) < N;
                const float* sb = pb ? (W + (size_t)(n0 + row) * K + kt + q * 4) : W;
                cp16(bB + row * 144 + q * 16, sb, pb);
            }
        }
        asm volatile("cp.async.commit_group;\n" ::: "memory");
    };

    stage(0, 0);
    for (int c = 0; c < nch; c++) {
        if (c + 1 < nch) {
            stage(c + 1, (c + 1) & 1);
            asm volatile("cp.async.wait_group 1;" ::: "memory");
        } else {
            asm volatile("cp.async.wait_group 0;" ::: "memory");
        }
        __syncthreads();

        const uint32_t (*sA)[36] =
            (const uint32_t (*)[36])(dsm + (c & 1) * GBUF);
        const uint32_t (*sB)[36] =
            (const uint32_t (*)[36])(dsm + 2 * GBUF + (c & 1) * GBUF);

#pragma unroll
        for (int ks = 0; ks < 4; ks++) {
            const int kk = ks * 8;
            uint32_t af[4][4], bf[8][2];
#pragma unroll
            for (int mt = 0; mt < 4; mt++) {
                int rb = wm + mt * 16;
                af[mt][0] = sA[rb + g][kk + tg];
                af[mt][1] = sA[rb + g + 8][kk + tg];
                af[mt][2] = sA[rb + g][kk + tg + 4];
                af[mt][3] = sA[rb + g + 8][kk + tg + 4];
            }
#pragma unroll
            for (int nt = 0; nt < 8; nt++) {
                int nb = wn + nt * 8;
                bf[nt][0] = sB[nb + g][kk + tg];
                bf[nt][1] = sB[nb + g][kk + tg + 4];
            }
#pragma unroll
            for (int mt = 0; mt < 4; mt++)
#pragma unroll
                for (int nt = 0; nt < 8; nt++)
                    mma_tf32(acc[mt][nt], af[mt], bf[nt]);
        }
        __syncthreads();
    }

    const bool n_even_full = ((N & 1) == 0);
#pragma unroll
    for (int mt = 0; mt < 4; mt++) {
        int row = m0 + wm + mt * 16 + g;
#pragma unroll
        for (int nt = 0; nt < 8; nt++) {
            int col = n0 + wn + nt * 8 + tg * 2;
            const float* c0 = &acc[mt][nt][0];
            if (n_even_full && col + 1 < N) {
                float b0 = bias ? __ldg(bias + col) : 0.f;
                float b1 = bias ? __ldg(bias + col + 1) : 0.f;
                *(float2*)(C + (size_t)row * N + col) =
                    make_float2(c0[0] + b0, c0[1] + b1);
                *(float2*)(C + (size_t)(row + 8) * N + col) =
                    make_float2(c0[2] + b0, c0[3] + b1);
            } else {
                if (col < N) {
                    float b0 = bias ? __ldg(bias + col) : 0.f;
                    C[(size_t)row * N + col]       = c0[0] + b0;
                    C[(size_t)(row + 8) * N + col] = c0[2] + b0;
                }
                if (col + 1 < N) {
                    float b1 = bias ? __ldg(bias + col + 1) : 0.f;
                    C[(size_t)row * N + col + 1]       = c0[1] + b1;
                    C[(size_t)(row + 8) * N + col + 1] = c0[3] + b1;
                }
            }
        }
    }
}

// ---------------- scoring GEMM: out = avec @ emb[1:].T ----------------------
// One CTA per 128-col N-strip; W tile persisted in smem (cvt from RAW emb),
// loops over all 8 M-tiles of avec (A is L2-resident).
// 256 threads = 8 warps (2M x 4N, warp tile 64x32).
#define SCORE_SMEM (2 * 4 * 18432)
__global__ void __launch_bounds__(256, 1)
gemm_score_kernel(const float* __restrict__ A,   // [1024,128] tf32-rounded
                  const float* __restrict__ W,   // raw emb+Hh, [99999,128]
                  float* __restrict__ C) {       // [1024, 99999]
    extern __shared__ char dsm[];
    uint32_t (*sW)[128][36] = (uint32_t (*)[128][36])dsm;
    uint32_t (*sA)[128][36] = (uint32_t (*)[128][36])(dsm + 4 * 18432);

    const int tid  = threadIdx.x;
    const int warp = tid >> 5, lane = tid & 31;
    const int g  = lane >> 2, tg = lane & 3;
    const int wm = (warp & 1) * 64;
    const int wn = (warp >> 1) * 32;
    const int n0 = blockIdx.x * 128;

    // persist W tile, converting raw fp32 -> tf32 once
    for (int i = tid; i < 128 * 32; i += 256) {
        int row = i >> 5, q = i & 31;
        int ch = q >> 3, qq = q & 7;
        float4 v = make_float4(0.f, 0.f, 0.f, 0.f);
        if (n0 + row < V1)
            v = *(const float4*)(W + (size_t)(n0 + row) * Hh + q * 4);
        uint32_t* d = &sW[ch][row][qq * 4];
        d[0] = f2tf32(v.x); d[1] = f2tf32(v.y);
        d[2] = f2tf32(v.z); d[3] = f2tf32(v.w);
    }

    for (int mt = 0; mt < 8; mt++) {
        const int m0 = mt * 128;
        // stage A tile (already tf32-rounded values; raw bit copy)
        for (int i = tid; i < 128 * 32; i += 256) {
            int row = i >> 5, q = i & 31;
            int ch = q >> 3, qq = q & 7;
            float4 v = *(const float4*)(A + (size_t)(m0 + row) * Hh + q * 4);
            uint32_t* d = &sA[ch][row][qq * 4];
            d[0] = __float_as_uint(v.x); d[1] = __float_as_uint(v.y);
            d[2] = __float_as_uint(v.z); d[3] = __float_as_uint(v.w);
        }
        __syncthreads();

        float acc[4][4][4];
#pragma unroll
        for (int a = 0; a < 4; a++)
#pragma unroll
            for (int b = 0; b < 4; b++)
#pragma unroll
                for (int i = 0; i < 4; i++) acc[a][b][i] = 0.f;

#pragma unroll
        for (int ch = 0; ch < 4; ch++) {
#pragma unroll
            for (int ks = 0; ks < 4; ks++) {
                const int kk = ks * 8;
                uint32_t af[4][4], bf[4][2];
#pragma unroll
                for (int a = 0; a < 4; a++) {
                    int rb = wm + a * 16;
                    af[a][0] = sA[ch][rb + g][kk + tg];
                    af[a][1] = sA[ch][rb + g + 8][kk + tg];
                    af[a][2] = sA[ch][rb + g][kk + tg + 4];
                    af[a][3] = sA[ch][rb + g + 8][kk + tg + 4];
                }
#pragma unroll
                for (int b = 0; b < 4; b++) {
                    int nb = wn + b * 8;
                    bf[b][0] = sW[ch][nb + g][kk + tg];
                    bf[b][1] = sW[ch][nb + g][kk + tg + 4];
                }
#pragma unroll
                for (int a = 0; a < 4; a++)
#pragma unroll
                    for (int b = 0; b < 4; b++)
                        mma_tf32(acc[a][b], af[a], bf[b]);
            }
        }

        // epilogue (N = 99999 odd -> scalar stores)
#pragma unroll
        for (int a = 0; a < 4; a++) {
            int row = m0 + wm + a * 16 + g;
#pragma unroll
            for (int b = 0; b < 4; b++) {
                int col = n0 + wn + b * 8 + tg * 2;
                const float* c0 = &acc[a][b][0];
                if (col < V1) {
                    C[(size_t)row * V1 + col]       = c0[0];
                    C[(size_t)(row + 8) * V1 + col] = c0[2];
                }
                if (col + 1 < V1) {
                    C[(size_t)row * V1 + col + 1]       = c0[1];
                    C[(size_t)(row + 8) * V1 + col + 1] = c0[3];
                }
            }
        }
        __syncthreads();
    }
}

// ---------------- h = round(emb[items]) --------------------------------------
__global__ void gather_kernel(const int* __restrict__ items,
                              const float* __restrict__ emb,
                              float* __restrict__ h, int total4) {
    int i = blockIdx.x * blockDim.x + threadIdx.x;
    if (i >= total4) return;
    int bn = i >> 5, q = i & 31;
    int it = items[bn];
    float4 v = ((const float4*)emb)[(size_t)it * 32 + q];
    ((float4*)h)[i] = make_float4(roundtf(v.x), roundtf(v.y),
                                  roundtf(v.z), roundtf(v.w));
}

// ---------------- batched adjacency matmul (2-row register blocking) ---------
__global__ void amm_kernel(const float* __restrict__ Amat,
                           const float* __restrict__ cat,
                           const float* __restrict__ b_iah,
                           const float* __restrict__ b_oah,
                           float* __restrict__ inputs) {
    int b = blockIdx.x;
    int tid = threadIdx.x;                 // 256 threads
    __shared__ float sA[Nn * Nn];
    __shared__ __align__(16) float sH[Nn * Hh];
    const float* Ab = Amat + (size_t)b * Nn * 2 * Nn;

#pragma unroll
    for (int pass = 0; pass < 2; pass++) {
        const float* bias = pass ? b_oah : b_iah;
        int acol = pass ? Nn : 0;
        for (int i = tid; i < Nn * Nn; i += 256)
            sA[i] = Ab[(i / Nn) * (2 * Nn) + acol + (i % Nn)];
        for (int i = tid; i < Nn * (Hh / 4); i += 256) {
            int k = i >> 5, q = i & 31;
            ((float4*)sH)[i] =
                ((const float4*)cat)[((size_t)b * Nn + k) * 160 + pass * 32 + q];
        }
        __syncthreads();
        for (int o = tid; o < 25 * 32; o += 256) {
            int n = o >> 5, q = o & 31;
            float4 bq = *(const float4*)(bias + q * 4);
            float4 a0 = bq, a1 = bq;
#pragma unroll 10
            for (int k = 0; k < Nn; k++) {
                float4 hv = *(const float4*)&sH[k * Hh + q * 4];
                float w0 = sA[n * Nn + k];
                float w1 = sA[(n + 25) * Nn + k];
                a0.x += w0 * hv.x; a0.y += w0 * hv.y;
                a0.z += w0 * hv.z; a0.w += w0 * hv.w;
                a1.x += w1 * hv.x; a1.y += w1 * hv.y;
                a1.z += w1 * hv.z; a1.w += w1 * hv.w;
            }
            a0.x = roundtf(a0.x); a0.y = roundtf(a0.y);
            a0.z = roundtf(a0.z); a0.w = roundtf(a0.w);
            a1.x = roundtf(a1.x); a1.y = roundtf(a1.y);
            a1.z = roundtf(a1.z); a1.w = roundtf(a1.w);
            *(float4*)(inputs + ((size_t)b * Nn + n) * (2 * Hh) + pass * Hh + q * 4) = a0;
            *(float4*)(inputs + ((size_t)b * Nn + n + 25) * (2 * Hh) + pass * Hh + q * 4) = a1;
        }
        __syncthreads();
    }
}

// ---------------- GRU gate math ----------------------------------------------
__global__ void gru_kernel(const float* __restrict__ gi,
                           const float* __restrict__ cat,
                           const float* __restrict__ h,
                           float* __restrict__ newh, int total) {
    int i = blockIdx.x * blockDim.x + threadIdx.x;
    if (i >= total) return;
    int bn = i / Hh, hh = i - bn * Hh;
    size_t gibase = (size_t)bn * 3 * Hh;
    size_t cbase  = (size_t)bn * 640;
    float i_r = gi[gibase + hh];
    float i_i = gi[gibase + Hh + hh];
    float i_n = gi[gibase + 2 * Hh + hh];
    float h_r = cat[cbase + 256 + hh];
    float h_i = cat[cbase + 384 + hh];
    float h_n = cat[cbase + 512 + hh];
    float r = 1.f / (1.f + expf(-(i_r + h_r)));
    float z = 1.f / (1.f + expf(-(i_i + h_i)));
    float ng = tanhf(i_n + r * h_n);
    newh[i] = roundtf(ng + z * (h[i] - ng));
}

// ---------------- alias gather + ht ------------------------------------------
__global__ void seq_kernel(const int* __restrict__ alias,
                           const int* __restrict__ mask,
                           const float* __restrict__ newh,
                           float* __restrict__ seqh,
                           float* __restrict__ ht) {
    int b = blockIdx.x;
    int tid = threadIdx.x;                 // 256
    __shared__ int sal[Ss];
    __shared__ int slast;
    if (tid < Ss) sal[tid] = alias[b * Ss + tid];
    if (tid == 0) {
        int c = 0;
        for (int s = 0; s < Ss; s++) c += mask[b * Ss + s];
        slast = c - 1;
    }
    __syncthreads();
    const float4* src = (const float4*)newh + (size_t)b * Nn * (Hh / 4);
    float4* dst = (float4*)seqh + (size_t)b * Ss * (Hh / 4);
    for (int i = tid; i < Ss * (Hh / 4); i += 256) {
        int s = i >> 5, q = i & 31;
        dst[i] = src[sal[s] * 32 + q];
    }
    if (tid < 32) {
        const float4* hrow = (const float4*)newh + ((size_t)b * Nn + sal[slast]) * (Hh / 4);
        ((float4*)ht)[(size_t)b * (Hh / 4) + tid] = hrow[tid];
    }
}

// ---------------- attention readout ------------------------------------------
__global__ void attn_kernel(const float* __restrict__ q1,
                            const float* __restrict__ q2,
                            const float* __restrict__ fc3_w,
                            const float* __restrict__ seqh,
                            const int* __restrict__ mask,
                            float* __restrict__ avec) {
    int b = blockIdx.x;
    int tid = threadIdx.x;                 // 128
    int warp = tid >> 5, lane = tid & 31;
    __shared__ float salpha[Ss];
    for (int s = warp; s < Ss; s += 4) {
        float part = 0.f;
        for (int hh = lane; hh < Hh; hh += 32) {
            float v = q1[(size_t)b * Hh + hh] + q2[((size_t)b * Ss + s) * Hh + hh];
            part += fc3_w[hh] / (1.f + expf(-v));
        }
#pragma unroll
        for (int off = 16; off; off >>= 1)
            part += __shfl_down_sync(0xffffffffu, part, off);
        if (lane == 0) salpha[s] = part;
    }
    __syncthreads();
    int hh = tid;
    float acc = 0.f;
    for (int s = 0; s < Ss; s++) {
        float m = (float)mask[b * Ss + s];
        acc += salpha[s] * seqh[((size_t)b * Ss + s) * Hh + hh] * m;
    }
    avec[(size_t)b * Hh + hh] = roundtf(acc);
}

// ---------------- launch -----------------------------------------------------
extern "C" void kernel_launch(void* const* d_in, const int* in_sizes, int n_in,
                              void* d_out, int out_size) {
    const int*   alias_inputs = (const int*)  d_in[0];
    const float* A            = (const float*)d_in[1];
    const int*   items        = (const int*)  d_in[2];
    const int*   mask         = (const int*)  d_in[3];
    const float* emb          = (const float*)d_in[4];
    const float* ein_w        = (const float*)d_in[5];
    const float* ein_b        = (const float*)d_in[6];
    const float* eou_w        = (const float*)d_in[7];
    const float* eou_b        = (const float*)d_in[8];
    const float* w_ih         = (const float*)d_in[9];
    const float* w_hh         = (const float*)d_in[10];
    const float* b_ih         = (const float*)d_in[11];
    const float* b_hh         = (const float*)d_in[12];
    const float* b_iah        = (const float*)d_in[13];
    const float* b_oah        = (const float*)d_in[14];
    const float* fc1_w        = (const float*)d_in[15];
    const float* fc1_b        = (const float*)d_in[16];
    const float* fc2_w        = (const float*)d_in[17];
    const float* fc2_b        = (const float*)d_in[18];
    const float* fc3_w        = (const float*)d_in[19];
    float* out = (float*)d_out;

    cudaFuncSetAttribute(gemm2_kernel,
                         cudaFuncAttributeMaxDynamicSharedMemorySize, 4 * GBUF);
    cudaFuncSetAttribute(gemm_score_kernel,
                         cudaFuncAttributeMaxDynamicSharedMemorySize, SCORE_SMEM);

    float *p_h, *p_cat, *p_inputs, *p_gi, *p_newh;
    float *p_seqh, *p_ht, *p_q1, *p_q2, *p_avec, *p_wr, *p_bcat;
    cudaGetSymbolAddress((void**)&p_h,      g_h);
    cudaGetSymbolAddress((void**)&p_cat,    g_cat);
    cudaGetSymbolAddress((void**)&p_inputs, g_inputs);
    cudaGetSymbolAddress((void**)&p_gi,     g_gi);
    cudaGetSymbolAddress((void**)&p_newh,   g_newh);
    cudaGetSymbolAddress((void**)&p_seqh,   g_seqh);
    cudaGetSymbolAddress((void**)&p_ht,     g_ht);
    cudaGetSymbolAddress((void**)&p_q1,     g_q1);
    cudaGetSymbolAddress((void**)&p_q2,     g_q2);
    cudaGetSymbolAddress((void**)&p_avec,   g_avec);
    cudaGetSymbolAddress((void**)&p_wr,     g_wr);
    cudaGetSymbolAddress((void**)&p_bcat,   g_bcat);

    const int BN = Bb * Nn;                // 51200 = 400 * 128
    const int SM = 4 * GBUF;

    // 0. prep: pack cat weights, round small weights (emb rounding eliminated)
    pack_cat_kernel<<<(640 * 32 + 255) / 256, 256>>>(
        ein_w, eou_w, w_hh, ein_b, eou_b, b_hh, p_wr + WR_CAT, p_bcat);
    round_kernel<<<(98304 / 4 + 255) / 256, 256>>>(w_ih,  p_wr + WR_WIH, 98304 / 4);
    round_kernel<<<(16384 / 4 + 255) / 256, 256>>>(fc1_w, p_wr + WR_FC1, 16384 / 4);
    round_kernel<<<(16384 / 4 + 255) / 256, 256>>>(fc2_w, p_wr + WR_FC2, 16384 / 4);
    // 1. gather (rounds inline from raw emb)
    {
        int total4 = BN * (Hh / 4);
        gather_kernel<<<(total4 + 255) / 256, 256>>>(items, emb, p_h, total4);
    }
    // 2. cat GEMM: [hin|hout|gh] = h @ [ein;eou;whh]^T  (M=51200, N=640, K=128)
    gemm2_kernel<<<dim3(5, BN / 128), 128, SM>>>(p_h, p_wr + WR_CAT, p_bcat,
                                                 p_cat, BN, 640, Hh);
    // 3. adjacency matmuls
    amm_kernel<<<Bb, 256>>>(A, p_cat, b_iah, b_oah, p_inputs);
    // 4. gi  (N=384, K=256)
    gemm2_kernel<<<dim3(3, BN / 128), 128, SM>>>(p_inputs, p_wr + WR_WIH, b_ih,
                                                 p_gi, BN, 3 * Hh, 2 * Hh);
    // 5. GRU
    {
        int total = BN * Hh;
        gru_kernel<<<(total + 255) / 256, 256>>>(p_gi, p_cat, p_h, p_newh, total);
    }
    // 6. seq gather + ht
    seq_kernel<<<Bb, 256>>>(alias_inputs, mask, p_newh, p_seqh, p_ht);
    // 7. q1 (M=1024, N=128, K=128)
    gemm2_kernel<<<dim3(1, Bb / 128), 128, SM>>>(p_ht, p_wr + WR_FC1, fc1_b,
                                                 p_q1, Bb, Hh, Hh);
    // 8. q2 (M=51200, N=128, K=128)
    gemm2_kernel<<<dim3(1, BN / 128), 128, SM>>>(p_seqh, p_wr + WR_FC2, fc2_b,
                                                 p_q2, Bb * Ss, Hh, Hh);
    // 9. attention
    attn_kernel<<<Bb, 128>>>(p_q1, p_q2, fc3_w, p_seqh, mask, p_avec);
    // 10. scoring: out = avec @ emb[1:].T  (persistent-W kernel, raw emb)
    gemm_score_kernel<<<(V1 + 127) / 128, 256, SCORE_SMEM>>>(p_avec, emb + Hh, out);
    (void)in_sizes; (void)n_in; (void)out_size;
}

// round 10
// speedup vs baseline: 1.1977x; 1.1977x over previous
#include <cuda_runtime.h>
#include <cuda_bf16.h>
#include <cstdint>

// SR-GNN forward. Shapes fixed: B=1024, N=50, S=50, H=128, V=100000
#define Bb 1024
#define Nn 50
#define Ss 50
#define Hh 128
#define Vv 100000
#define V1 (Vv - 1)

// ---------------- scratch ---------------------------------------------------
__device__ float g_h     [Bb * Nn * Hh];
__device__ float g_cat   [Bb * Nn * 640];     // [hin(128) | hout(128) | gh(384)]
__device__ float g_inputs[Bb * Nn * 2 * Hh];
__device__ float g_gi    [Bb * Nn * 3 * Hh];
__device__ float g_newh  [Bb * Nn * Hh];
__device__ float g_ht    [Bb * Hh];
__device__ float g_q1    [Bb * Hh];
__device__ float g_nq    [Bb * Nn * Hh];      // newh @ fc2^T (q2 gathered later)
__device__ float g_avec  [Bb * Hh];
__device__ float g_wr    [212992];            // packed tf32-rounded weights
__device__ float g_bcat  [640];               // packed bias for cat GEMM

// packed weight offsets (floats)
#define WR_CAT 0                  // 640x128 = 81920
#define WR_WIH 81920              // 384x256 = 98304
#define WR_FC1 180224             // 128x128 = 16384
#define WR_FC2 196608             // 128x128 = 16384

// ---------------- tf32 helpers ----------------------------------------------
__device__ __forceinline__ uint32_t f2tf32(float x) {
    uint32_t r;
    asm("cvt.rna.tf32.f32 %0, %1;" : "=r"(r) : "f"(x));
    return r;
}
__device__ __forceinline__ float roundtf(float x) {
    return __uint_as_float(f2tf32(x));
}
__device__ __forceinline__ void mma_tf32(float* c, const uint32_t* a,
                                         const uint32_t* b) {
    asm volatile(
        "mma.sync.aligned.m16n8k8.row.col.f32.tf32.tf32.f32 "
        "{%0,%1,%2,%3}, {%4,%5,%6,%7}, {%8,%9}, {%0,%1,%2,%3};"
        : "+f"(c[0]), "+f"(c[1]), "+f"(c[2]), "+f"(c[3])
        : "r"(a[0]), "r"(a[1]), "r"(a[2]), "r"(a[3]), "r"(b[0]), "r"(b[1]));
}
__device__ __forceinline__ void cp16(uint32_t dst, const void* src, bool pred) {
    int sz = pred ? 16 : 0;
    asm volatile("cp.async.cg.shared.global [%0], [%1], 16, %2;\n"
                 :: "r"(dst), "l"(src), "r"(sz));
}

// ---------------- prep kernels ----------------------------------------------
// one launch rounds w_ih, fc1_w, fc2_w into packed buffer
__global__ void round_all_kernel(const float* __restrict__ w_ih,
                                 const float* __restrict__ fc1_w,
                                 const float* __restrict__ fc2_w,
                                 float* __restrict__ wr) {
    int i = blockIdx.x * blockDim.x + threadIdx.x;   // 32768 float4s
    if (i >= 32768) return;
    const float4* src;
    float4* dst;
    if (i < 24576)      { src = (const float4*)w_ih + i;
                          dst = (float4*)(wr + WR_WIH) + i; }
    else if (i < 28672) { src = (const float4*)fc1_w + (i - 24576);
                          dst = (float4*)(wr + WR_FC1) + (i - 24576); }
    else                { src = (const float4*)fc2_w + (i - 28672);
                          dst = (float4*)(wr + WR_FC2) + (i - 28672); }
    float4 v = *src;
    *dst = make_float4(roundtf(v.x), roundtf(v.y), roundtf(v.z), roundtf(v.w));
}

// pack [ein_w; eou_w; w_hh] rows (640x128) rounded + bias
__global__ void pack_cat_kernel(const float* __restrict__ ein_w,
                                const float* __restrict__ eou_w,
                                const float* __restrict__ w_hh,
                                const float* __restrict__ ein_b,
                                const float* __restrict__ eou_b,
                                const float* __restrict__ b_hh,
                                float* __restrict__ wcat,
                                float* __restrict__ bcat) {
    int i = blockIdx.x * blockDim.x + threadIdx.x;   // 640*32 float4s
    if (i < 640 * 32) {
        int r = i >> 5, q = i & 31;
        const float* src = (r < 128) ? (ein_w + (size_t)r * Hh)
                         : (r < 256) ? (eou_w + (size_t)(r - 128) * Hh)
                                     : (w_hh + (size_t)(r - 256) * Hh);
        float4 v = ((const float4*)src)[q];
        ((float4*)wcat)[i] = make_float4(roundtf(v.x), roundtf(v.y),
                                         roundtf(v.z), roundtf(v.w));
    }
    if (i < 640) {
        bcat[i] = (i < 128) ? ein_b[i]
                : (i < 256) ? eou_b[i - 128]
                            : b_hh[i - 256];
    }
}

// ---------------- HMMA tf32 GEMM (generic) ----------------------------------
// C[M,N] = A[M,K] @ W[N,K]^T (+bias). Inputs pre-rounded to tf32.
// CTA 128x128, 128 threads = 4 warps (2x2 of 64x64), BK=32, double-buffered.
#define GBUF 18432
__global__ void __launch_bounds__(128, 2)
gemm2_kernel(const float* __restrict__ A, const float* __restrict__ W,
             const float* __restrict__ bias, float* __restrict__ C,
             int M, int N, int K) {
    extern __shared__ char dsm[];
    const uint32_t sbase = (uint32_t)__cvta_generic_to_shared(dsm);
    const int tid  = threadIdx.x;
    const int warp = tid >> 5, lane = tid & 31;
    const int g  = lane >> 2;
    const int tg = lane & 3;
    const int wm = (warp & 1) * 64;
    const int wn = (warp >> 1) * 64;
    const int m0 = blockIdx.y * 128;
    const int n0 = blockIdx.x * 128;

    float acc[4][8][4];
#pragma unroll
    for (int mt = 0; mt < 4; mt++)
#pragma unroll
        for (int nt = 0; nt < 8; nt++)
#pragma unroll
            for (int i = 0; i < 4; i++) acc[mt][nt][i] = 0.f;

    const int nch = K >> 5;

    auto stage = [&](int c, int s) {
        const int kt = c * 32;
        uint32_t aB = sbase + s * GBUF;
        uint32_t bB = sbase + 2 * GBUF + s * GBUF;
#pragma unroll
        for (int i = 0; i < 4; i++) {
            int idx = tid + i * 128;
#pragma unroll
            for (int h = 0; h < 2; h++) {
                int id2 = idx + h * 512;
                int row = id2 >> 3, q = id2 & 7;
                bool pa = (m0 + row) < M;
                const float* sa = pa ? (A + (size_t)(m0 + row) * K + kt + q * 4) : A;
                cp16(aB + row * 144 + q * 16, sa, pa);
                bool pb = (n0 + row) < N;
                const float* sb = pb ? (W + (size_t)(n0 + row) * K + kt + q * 4) : W;
                cp16(bB + row * 144 + q * 16, sb, pb);
            }
        }
        asm volatile("cp.async.commit_group;\n" ::: "memory");
    };

    stage(0, 0);
    for (int c = 0; c < nch; c++) {
        if (c + 1 < nch) {
            stage(c + 1, (c + 1) & 1);
            asm volatile("cp.async.wait_group 1;" ::: "memory");
        } else {
            asm volatile("cp.async.wait_group 0;" ::: "memory");
        }
        __syncthreads();

        const uint32_t (*sA)[36] =
            (const uint32_t (*)[36])(dsm + (c & 1) * GBUF);
        const uint32_t (*sB)[36] =
            (const uint32_t (*)[36])(dsm + 2 * GBUF + (c & 1) * GBUF);

#pragma unroll
        for (int ks = 0; ks < 4; ks++) {
            const int kk = ks * 8;
            uint32_t af[4][4], bf[8][2];
#pragma unroll
            for (int mt = 0; mt < 4; mt++) {
                int rb = wm + mt * 16;
                af[mt][0] = sA[rb + g][kk + tg];
                af[mt][1] = sA[rb + g + 8][kk + tg];
                af[mt][2] = sA[rb + g][kk + tg + 4];
                af[mt][3] = sA[rb + g + 8][kk + tg + 4];
            }
#pragma unroll
            for (int nt = 0; nt < 8; nt++) {
                int nb = wn + nt * 8;
                bf[nt][0] = sB[nb + g][kk + tg];
                bf[nt][1] = sB[nb + g][kk + tg + 4];
            }
#pragma unroll
            for (int mt = 0; mt < 4; mt++)
#pragma unroll
                for (int nt = 0; nt < 8; nt++)
                    mma_tf32(acc[mt][nt], af[mt], bf[nt]);
        }
        __syncthreads();
    }

    const bool n_even_full = ((N & 1) == 0);
#pragma unroll
    for (int mt = 0; mt < 4; mt++) {
        int row = m0 + wm + mt * 16 + g;
#pragma unroll
        for (int nt = 0; nt < 8; nt++) {
            int col = n0 + wn + nt * 8 + tg * 2;
            const float* c0 = &acc[mt][nt][0];
            if (n_even_full && col + 1 < N) {
                float b0 = bias ? __ldg(bias + col) : 0.f;
                float b1 = bias ? __ldg(bias + col + 1) : 0.f;
                *(float2*)(C + (size_t)row * N + col) =
                    make_float2(c0[0] + b0, c0[1] + b1);
                *(float2*)(C + (size_t)(row + 8) * N + col) =
                    make_float2(c0[2] + b0, c0[3] + b1);
            } else {
                if (col < N) {
                    float b0 = bias ? __ldg(bias + col) : 0.f;
                    C[(size_t)row * N + col]       = c0[0] + b0;
                    C[(size_t)(row + 8) * N + col] = c0[2] + b0;
                }
                if (col + 1 < N) {
                    float b1 = bias ? __ldg(bias + col + 1) : 0.f;
                    C[(size_t)row * N + col + 1]       = c0[1] + b1;
                    C[(size_t)(row + 8) * N + col + 1] = c0[3] + b1;
                }
            }
        }
    }
}

// ---------------- scoring GEMM wrapper (W = raw emb, rounded on stage) -------
// Same structure as gemm2 but converts W to tf32 in registers after cp.async
// is not possible; instead W rows are raw fp32 — we round A-side only.
// NOTE: raw-vs-rounded W changes products by <= 2^-11 relative; to keep
// rel_err identical to prior rounds we pre-round emb is AVOIDED; instead the
// scoring GEMM uses the gemm2 path with a rounded W produced... (see launch:
// we simply reuse gemm2 with raw emb — tf32 mma ignores low mantissa bits,
// cvt.rna vs truncation differs in last tf32 ulp; measured rel_err kept
// passing in rounds 4-6 with rna; truncation risk not taken: we round here.)
__global__ void round_emb_kernel(const float* __restrict__ src,
                                 float* __restrict__ dst, int n4) {
    int i = blockIdx.x * blockDim.x + threadIdx.x;
    if (i >= n4) return;
    float4 v = ((const float4*)src)[i];
    ((float4*)dst)[i] = make_float4(roundtf(v.x), roundtf(v.y),
                                    roundtf(v.z), roundtf(v.w));
}
__device__ float g_embr[Vv * Hh];

// ---------------- h = round(emb[items]) --------------------------------------
__global__ void gather_kernel(const int* __restrict__ items,
                              const float* __restrict__ emb,
                              float* __restrict__ h, int total4) {
    int i = blockIdx.x * blockDim.x + threadIdx.x;
    if (i >= total4) return;
    int bn = i >> 5, q = i & 31;
    int it = items[bn];
    float4 v = ((const float4*)emb)[(size_t)it * 32 + q];
    ((float4*)h)[i] = make_float4(roundtf(v.x), roundtf(v.y),
                                  roundtf(v.z), roundtf(v.w));
}

// ---------------- batched adjacency matmul (2-row register blocking) ---------
__global__ void amm_kernel(const float* __restrict__ Amat,
                           const float* __restrict__ cat,
                           const float* __restrict__ b_iah,
                           const float* __restrict__ b_oah,
                           float* __restrict__ inputs) {
    int b = blockIdx.x;
    int tid = threadIdx.x;                 // 256 threads
    __shared__ float sA[Nn * Nn];
    __shared__ __align__(16) float sH[Nn * Hh];
    const float* Ab = Amat + (size_t)b * Nn * 2 * Nn;

#pragma unroll
    for (int pass = 0; pass < 2; pass++) {
        const float* bias = pass ? b_oah : b_iah;
        int acol = pass ? Nn : 0;
        for (int i = tid; i < Nn * Nn; i += 256)
            sA[i] = Ab[(i / Nn) * (2 * Nn) + acol + (i % Nn)];
        for (int i = tid; i < Nn * (Hh / 4); i += 256) {
            int k = i >> 5, q = i & 31;
            ((float4*)sH)[i] =
                ((const float4*)cat)[((size_t)b * Nn + k) * 160 + pass * 32 + q];
        }
        __syncthreads();
        for (int o = tid; o < 25 * 32; o += 256) {
            int n = o >> 5, q = o & 31;
            float4 bq = *(const float4*)(bias + q * 4);
            float4 a0 = bq, a1 = bq;
#pragma unroll 10
            for (int k = 0; k < Nn; k++) {
                float4 hv = *(const float4*)&sH[k * Hh + q * 4];
                float w0 = sA[n * Nn + k];
                float w1 = sA[(n + 25) * Nn + k];
                a0.x += w0 * hv.x; a0.y += w0 * hv.y;
                a0.z += w0 * hv.z; a0.w += w0 * hv.w;
                a1.x += w1 * hv.x; a1.y += w1 * hv.y;
                a1.z += w1 * hv.z; a1.w += w1 * hv.w;
            }
            a0.x = roundtf(a0.x); a0.y = roundtf(a0.y);
            a0.z = roundtf(a0.z); a0.w = roundtf(a0.w);
            a1.x = roundtf(a1.x); a1.y = roundtf(a1.y);
            a1.z = roundtf(a1.z); a1.w = roundtf(a1.w);
            *(float4*)(inputs + ((size_t)b * Nn + n) * (2 * Hh) + pass * Hh + q * 4) = a0;
            *(float4*)(inputs + ((size_t)b * Nn + n + 25) * (2 * Hh) + pass * Hh + q * 4) = a1;
        }
        __syncthreads();
    }
}

// ---------------- GRU gate math ----------------------------------------------
__global__ void gru_kernel(const float* __restrict__ gi,
                           const float* __restrict__ cat,
                           const float* __restrict__ h,
                           float* __restrict__ newh, int total) {
    int i = blockIdx.x * blockDim.x + threadIdx.x;
    if (i >= total) return;
    int bn = i / Hh, hh = i - bn * Hh;
    size_t gibase = (size_t)bn * 3 * Hh;
    size_t cbase  = (size_t)bn * 640;
    float i_r = gi[gibase + hh];
    float i_i = gi[gibase + Hh + hh];
    float i_n = gi[gibase + 2 * Hh + hh];
    float h_r = cat[cbase + 256 + hh];
    float h_i = cat[cbase + 384 + hh];
    float h_n = cat[cbase + 512 + hh];
    float r = 1.f / (1.f + expf(-(i_r + h_r)));
    float z = 1.f / (1.f + expf(-(i_i + h_i)));
    float ng = tanhf(i_n + r * h_n);
    newh[i] = roundtf(ng + z * (h[i] - ng));
}

// ---------------- ht only (seqh materialization eliminated) ------------------
__global__ void ht_kernel(const int* __restrict__ alias,
                          const int* __restrict__ mask,
                          const float* __restrict__ newh,
                          float* __restrict__ ht) {
    int b = blockIdx.x;
    int lane = threadIdx.x;                // 32 threads
    int c = 0;
    if (lane < Ss)      c += mask[b * Ss + lane];
    if (lane + 32 < Ss) c += mask[b * Ss + lane + 32];
#pragma unroll
    for (int off = 16; off; off >>= 1)
        c += __shfl_down_sync(0xffffffffu, c, off);
    c = __shfl_sync(0xffffffffu, c, 0);
    int node = alias[b * Ss + (c - 1)];
    const float4* hrow = (const float4*)newh + ((size_t)b * Nn + node) * (Hh / 4);
    ((float4*)ht)[(size_t)b * (Hh / 4) + lane] = hrow[lane];
}

// ---------------- attention readout (gathers nq/newh via alias) --------------
__global__ void attn_kernel(const float* __restrict__ q1,
                            const float* __restrict__ nq,
                            const float* __restrict__ fc3_w,
                            const float* __restrict__ newh,
                            const int* __restrict__ alias,
                            const int* __restrict__ mask,
                            float* __restrict__ avec) {
    int b = blockIdx.x;
    int tid = threadIdx.x;                 // 128
    int warp = tid >> 5, lane = tid & 31;
    __shared__ float salpha[Ss];
    __shared__ int sal[Ss];
    if (tid < Ss) sal[tid] = alias[b * Ss + tid];
    __syncthreads();
    for (int s = warp; s < Ss; s += 4) {
        size_t rowbase = ((size_t)b * Nn + sal[s]) * Hh;
        float part = 0.f;
        for (int hh = lane; hh < Hh; hh += 32) {
            float v = q1[(size_t)b * Hh + hh] + nq[rowbase + hh];
            part += fc3_w[hh] / (1.f + expf(-v));
        }
#pragma unroll
        for (int off = 16; off; off >>= 1)
            part += __shfl_down_sync(0xffffffffu, part, off);
        if (lane == 0) salpha[s] = part;
    }
    __syncthreads();
    int hh = tid;
    float acc = 0.f;
    for (int s = 0; s < Ss; s++) {
        float m = (float)mask[b * Ss + s];
        acc += salpha[s] * newh[((size_t)b * Nn + sal[s]) * Hh + hh] * m;
    }
    avec[(size_t)b * Hh + hh] = roundtf(acc);
}

// ---------------- launch -----------------------------------------------------
extern "C" void kernel_launch(void* const* d_in, const int* in_sizes, int n_in,
                              void* d_out, int out_size) {
    const int*   alias_inputs = (const int*)  d_in[0];
    const float* A            = (const float*)d_in[1];
    const int*   items        = (const int*)  d_in[2];
    const int*   mask         = (const int*)  d_in[3];
    const float* emb          = (const float*)d_in[4];
    const float* ein_w        = (const float*)d_in[5];
    const float* ein_b        = (const float*)d_in[6];
    const float* eou_w        = (const float*)d_in[7];
    const float* eou_b        = (const float*)d_in[8];
    const float* w_ih         = (const float*)d_in[9];
    const float* w_hh         = (const float*)d_in[10];
    const float* b_ih         = (const float*)d_in[11];
    const float* b_hh         = (const float*)d_in[12];
    const float* b_iah        = (const float*)d_in[13];
    const float* b_oah        = (const float*)d_in[14];
    const float* fc1_w        = (const float*)d_in[15];
    const float* fc1_b        = (const float*)d_in[16];
    const float* fc2_w        = (const float*)d_in[17];
    const float* fc2_b        = (const float*)d_in[18];
    const float* fc3_w        = (const float*)d_in[19];
    float* out = (float*)d_out;

    cudaFuncSetAttribute(gemm2_kernel,
                         cudaFuncAttributeMaxDynamicSharedMemorySize, 4 * GBUF);

    float *p_h, *p_cat, *p_inputs, *p_gi, *p_newh;
    float *p_ht, *p_q1, *p_nq, *p_avec, *p_wr, *p_bcat, *p_embr;
    cudaGetSymbolAddress((void**)&p_h,      g_h);
    cudaGetSymbolAddress((void**)&p_cat,    g_cat);
    cudaGetSymbolAddress((void**)&p_inputs, g_inputs);
    cudaGetSymbolAddress((void**)&p_gi,     g_gi);
    cudaGetSymbolAddress((void**)&p_newh,   g_newh);
    cudaGetSymbolAddress((void**)&p_ht,     g_ht);
    cudaGetSymbolAddress((void**)&p_q1,     g_q1);
    cudaGetSymbolAddress((void**)&p_nq,     g_nq);
    cudaGetSymbolAddress((void**)&p_avec,   g_avec);
    cudaGetSymbolAddress((void**)&p_wr,     g_wr);
    cudaGetSymbolAddress((void**)&p_bcat,   g_bcat);
    cudaGetSymbolAddress((void**)&p_embr,   g_embr);

    const int BN = Bb * Nn;                // 51200 = 400 * 128
    const int SM = 4 * GBUF;

    // 0. prep: pack cat weights + one merged round for wih/fc1/fc2 + emb round
    pack_cat_kernel<<<(640 * 32 + 255) / 256, 256>>>(
        ein_w, eou_w, w_hh, ein_b, eou_b, b_hh, p_wr + WR_CAT, p_bcat);
    round_all_kernel<<<(32768 + 255) / 256, 256>>>(w_ih, fc1_w, fc2_w, p_wr);
    round_emb_kernel<<<(Vv * Hh / 4 + 255) / 256, 256>>>(emb, p_embr, Vv * Hh / 4);
    // 1. gather (rounds inline from raw emb)
    {
        int total4 = BN * (Hh / 4);
        gather_kernel<<<(total4 + 255) / 256, 256>>>(items, emb, p_h, total4);
    }
    // 2. cat GEMM: [hin|hout|gh] = h @ [ein;eou;whh]^T  (M=51200, N=640, K=128)
    gemm2_kernel<<<dim3(5, BN / 128), 128, SM>>>(p_h, p_wr + WR_CAT, p_bcat,
                                                 p_cat, BN, 640, Hh);
    // 3. adjacency matmuls
    amm_kernel<<<Bb, 256>>>(A, p_cat, b_iah, b_oah, p_inputs);
    // 4. gi  (N=384, K=256)
    gemm2_kernel<<<dim3(3, BN / 128), 128, SM>>>(p_inputs, p_wr + WR_WIH, b_ih,
                                                 p_gi, BN, 3 * Hh, 2 * Hh);
    // 5. GRU
    {
        int total = BN * Hh;
        gru_kernel<<<(total + 255) / 256, 256>>>(p_gi, p_cat, p_h, p_newh, total);
    }
    // 6. ht only (seqh eliminated)
    ht_kernel<<<Bb, 32>>>(alias_inputs, mask, p_newh, p_ht);
    // 7. q1 (M=1024, N=128, K=128)
    gemm2_kernel<<<dim3(1, Bb / 128), 128, SM>>>(p_ht, p_wr + WR_FC1, fc1_b,
                                                 p_q1, Bb, Hh, Hh);
    // 8. nq = newh @ fc2^T (+fc2_b)  (M=51200, N=128, K=128)
    gemm2_kernel<<<dim3(1, BN / 128), 128, SM>>>(p_newh, p_wr + WR_FC2, fc2_b,
                                                 p_nq, BN, Hh, Hh);
    // 9. attention (gathers nq/newh rows by alias)
    attn_kernel<<<Bb, 128>>>(p_q1, p_nq, fc3_w, p_newh, alias_inputs, mask, p_avec);
    // 10. scoring: out = avec @ emb[1:].T  (gemm2 path — known good)
    {
        gemm2_kernel<<<dim3((V1 + 127) / 128, Bb / 128), 128, SM>>>(
            p_avec, p_embr + Hh, nullptr, out, Bb, V1, Hh);
    }
    (void)in_sizes; (void)n_in; (void)out_size;
}

// round 12
// speedup vs baseline: 1.2431x; 1.0379x over previous
#include <cuda_runtime.h>
#include <cuda_bf16.h>
#include <cstdint>

// SR-GNN forward. Shapes fixed: B=1024, N=50, S=50, H=128, V=100000
#define Bb 1024
#define Nn 50
#define Ss 50
#define Hh 128
#define Vv 100000
#define V1 (Vv - 1)

// ---------------- scratch ---------------------------------------------------
__device__ float g_h     [Bb * Nn * Hh];
__device__ float g_cat   [Bb * Nn * 640];     // [hin(128) | hout(128) | gh(384)]
__device__ float g_inputs[Bb * Nn * 2 * Hh];
__device__ float g_gi    [Bb * Nn * 3 * Hh];
__device__ float g_newh  [Bb * Nn * Hh];
__device__ float g_ht    [Bb * Hh];
__device__ float g_q1    [Bb * Hh];
__device__ float g_nq    [Bb * Nn * Hh];
__device__ float g_avec  [Bb * Hh];
__device__ float g_wr    [212992];            // packed tf32-rounded weights
__device__ float g_bcat  [640];               // packed bias for cat GEMM

// packed weight offsets (floats)
#define WR_CAT 0                  // 640x128 = 81920
#define WR_WIH 81920              // 384x256 = 98304
#define WR_FC1 180224             // 128x128 = 16384
#define WR_FC2 196608             // 128x128 = 16384

// ---------------- tf32 helpers ----------------------------------------------
__device__ __forceinline__ uint32_t f2tf32(float x) {
    uint32_t r;
    asm("cvt.rna.tf32.f32 %0, %1;" : "=r"(r) : "f"(x));
    return r;
}
__device__ __forceinline__ uint32_t u2tf32(uint32_t x) {
    uint32_t r;
    asm("cvt.rna.tf32.f32 %0, %1;" : "=r"(r) : "r"(x));
    return r;
}
__device__ __forceinline__ float roundtf(float x) {
    return __uint_as_float(f2tf32(x));
}
__device__ __forceinline__ void mma_tf32(float* c, const uint32_t* a,
                                         const uint32_t* b) {
    asm volatile(
        "mma.sync.aligned.m16n8k8.row.col.f32.tf32.tf32.f32 "
        "{%0,%1,%2,%3}, {%4,%5,%6,%7}, {%8,%9}, {%0,%1,%2,%3};"
        : "+f"(c[0]), "+f"(c[1]), "+f"(c[2]), "+f"(c[3])
        : "r"(a[0]), "r"(a[1]), "r"(a[2]), "r"(a[3]), "r"(b[0]), "r"(b[1]));
}
__device__ __forceinline__ void cp16(uint32_t dst, const void* src, bool pred) {
    int sz = pred ? 16 : 0;
    asm volatile("cp.async.cg.shared.global [%0], [%1], 16, %2;\n"
                 :: "r"(dst), "l"(src), "r"(sz));
}

// ---------------- prep kernels ----------------------------------------------
__global__ void round_all_kernel(const float* __restrict__ w_ih,
                                 const float* __restrict__ fc1_w,
                                 const float* __restrict__ fc2_w,
                                 float* __restrict__ wr) {
    int i = blockIdx.x * blockDim.x + threadIdx.x;   // 32768 float4s
    if (i >= 32768) return;
    const float4* src;
    float4* dst;
    if (i < 24576)      { src = (const float4*)w_ih + i;
                          dst = (float4*)(wr + WR_WIH) + i; }
    else if (i < 28672) { src = (const float4*)fc1_w + (i - 24576);
                          dst = (float4*)(wr + WR_FC1) + (i - 24576); }
    else                { src = (const float4*)fc2_w + (i - 28672);
                          dst = (float4*)(wr + WR_FC2) + (i - 28672); }
    float4 v = *src;
    *dst = make_float4(roundtf(v.x), roundtf(v.y), roundtf(v.z), roundtf(v.w));
}

__global__ void pack_cat_kernel(const float* __restrict__ ein_w,
                                const float* __restrict__ eou_w,
                                const float* __restrict__ w_hh,
                                const float* __restrict__ ein_b,
                                const float* __restrict__ eou_b,
                                const float* __restrict__ b_hh,
                                float* __restrict__ wcat,
                                float* __restrict__ bcat) {
    int i = blockIdx.x * blockDim.x + threadIdx.x;   // 640*32 float4s
    if (i < 640 * 32) {
        int r = i >> 5, q = i & 31;
        const float* src = (r < 128) ? (ein_w + (size_t)r * Hh)
                         : (r < 256) ? (eou_w + (size_t)(r - 128) * Hh)
                                     : (w_hh + (size_t)(r - 256) * Hh);
        float4 v = ((const float4*)src)[q];
        ((float4*)wcat)[i] = make_float4(roundtf(v.x), roundtf(v.y),
                                         roundtf(v.z), roundtf(v.w));
    }
    if (i < 640) {
        bcat[i] = (i < 128) ? ein_b[i]
                : (i < 256) ? eou_b[i - 128]
                            : b_hh[i - 256];
    }
}

// ---------------- HMMA tf32 GEMM (generic, 3-stage pipeline) -----------------
// C[M,N] = A[M,K] @ W[N,K]^T (+bias).
// CVTB=false: W pre-rounded to tf32. CVTB=true: W raw fp32, rna-cvt applied to
// B fragments in-loop (bit-identical math to pre-rounding).
// CTA 128x128, 128 threads = 4 warps (2x2 of 64x64), BK=32, triple-buffered.
// Requires M%128==0, K%64==0 (>=2 chunks). N guarded.
#define GBUF 18432
template <bool CVTB>
__global__ void __launch_bounds__(128, 2)
gemm2_kernel(const float* __restrict__ A, const float* __restrict__ W,
             const float* __restrict__ bias, float* __restrict__ C,
             int M, int N, int K) {
    extern __shared__ char dsm[];
    const uint32_t sbase = (uint32_t)__cvta_generic_to_shared(dsm);
    const int tid  = threadIdx.x;
    const int warp = tid >> 5, lane = tid & 31;
    const int g  = lane >> 2;
    const int tg = lane & 3;
    const int wm = (warp & 1) * 64;
    const int wn = (warp >> 1) * 64;
    const int m0 = blockIdx.y * 128;
    const int n0 = blockIdx.x * 128;

    float acc[4][8][4];
#pragma unroll
    for (int mt = 0; mt < 4; mt++)
#pragma unroll
        for (int nt = 0; nt < 8; nt++)
#pragma unroll
            for (int i = 0; i < 4; i++) acc[mt][nt][i] = 0.f;

    const int nch = K >> 5;

    auto stage = [&](int c, int s) {
        const int kt = c * 32;
        uint32_t aB = sbase + s * GBUF;
        uint32_t bB = sbase + 3 * GBUF + s * GBUF;
#pragma unroll
        for (int i = 0; i < 4; i++) {
            int idx = tid + i * 128;
#pragma unroll
            for (int h = 0; h < 2; h++) {
                int id2 = idx + h * 512;
                int row = id2 >> 3, q = id2 & 7;
                bool pa = (m0 + row) < M;
                const float* sa = pa ? (A + (size_t)(m0 + row) * K + kt + q * 4) : A;
                cp16(aB + row * 144 + q * 16, sa, pa);
                bool pb = (n0 + row) < N;
                const float* sb = pb ? (W + (size_t)(n0 + row) * K + kt + q * 4) : W;
                cp16(bB + row * 144 + q * 16, sb, pb);
            }
        }
        asm volatile("cp.async.commit_group;\n" ::: "memory");
    };

    stage(0, 0);
    stage(1, 1);
    for (int c = 0; c < nch; c++) {
        if (c + 2 < nch) {
            stage(c + 2, (c + 2) % 3);
            asm volatile("cp.async.wait_group 2;" ::: "memory");
        } else if (c + 1 < nch) {
            asm volatile("cp.async.wait_group 1;" ::: "memory");
        } else {
            asm volatile("cp.async.wait_group 0;" ::: "memory");
        }
        __syncthreads();

        const uint32_t (*sA)[36] =
            (const uint32_t (*)[36])(dsm + (c % 3) * GBUF);
        const uint32_t (*sB)[36] =
            (const uint32_t (*)[36])(dsm + 3 * GBUF + (c % 3) * GBUF);

#pragma unroll
        for (int ks = 0; ks < 4; ks++) {
            const int kk = ks * 8;
            uint32_t af[4][4], bf[8][2];
#pragma unroll
            for (int mt = 0; mt < 4; mt++) {
                int rb = wm + mt * 16;
                af[mt][0] = sA[rb + g][kk + tg];
                af[mt][1] = sA[rb + g + 8][kk + tg];
                af[mt][2] = sA[rb + g][kk + tg + 4];
                af[mt][3] = sA[rb + g + 8][kk + tg + 4];
            }
#pragma unroll
            for (int nt = 0; nt < 8; nt++) {
                int nb = wn + nt * 8;
                uint32_t b0 = sB[nb + g][kk + tg];
                uint32_t b1 = sB[nb + g][kk + tg + 4];
                if (CVTB) { b0 = u2tf32(b0); b1 = u2tf32(b1); }
                bf[nt][0] = b0;
                bf[nt][1] = b1;
            }
#pragma unroll
            for (int mt = 0; mt < 4; mt++)
#pragma unroll
                for (int nt = 0; nt < 8; nt++)
                    mma_tf32(acc[mt][nt], af[mt], bf[nt]);
        }
        __syncthreads();
    }

    const bool n_even_full = ((N & 1) == 0);
#pragma unroll
    for (int mt = 0; mt < 4; mt++) {
        int row = m0 + wm + mt * 16 + g;
#pragma unroll
        for (int nt = 0; nt < 8; nt++) {
            int col = n0 + wn + nt * 8 + tg * 2;
            const float* c0 = &acc[mt][nt][0];
            if (n_even_full && col + 1 < N) {
                float b0 = bias ? __ldg(bias + col) : 0.f;
                float b1 = bias ? __ldg(bias + col + 1) : 0.f;
                *(float2*)(C + (size_t)row * N + col) =
                    make_float2(c0[0] + b0, c0[1] + b1);
                *(float2*)(C + (size_t)(row + 8) * N + col) =
                    make_float2(c0[2] + b0, c0[3] + b1);
            } else {
                if (col < N) {
                    float b0 = bias ? __ldg(bias + col) : 0.f;
                    C[(size_t)row * N + col]       = c0[0] + b0;
                    C[(size_t)(row + 8) * N + col] = c0[2] + b0;
                }
                if (col + 1 < N) {
                    float b1 = bias ? __ldg(bias + col + 1) : 0.f;
                    C[(size_t)row * N + col + 1]       = c0[1] + b1;
                    C[(size_t)(row + 8) * N + col + 1] = c0[3] + b1;
                }
            }
        }
    }
}

// ---------------- h = round(emb[items]) --------------------------------------
__global__ void gather_kernel(const int* __restrict__ items,
                              const float* __restrict__ emb,
                              float* __restrict__ h, int total4) {
    int i = blockIdx.x * blockDim.x + threadIdx.x;
    if (i >= total4) return;
    int bn = i >> 5, q = i & 31;
    int it = items[bn];
    float4 v = ((const float4*)emb)[(size_t)it * 32 + q];
    ((float4*)h)[i] = make_float4(roundtf(v.x), roundtf(v.y),
                                  roundtf(v.z), roundtf(v.w));
}

// ---------------- batched adjacency matmul -----------------------------------
__global__ void amm_kernel(const float* __restrict__ Amat,
                           const float* __restrict__ cat,
                           const float* __restrict__ b_iah,
                           const float* __restrict__ b_oah,
                           float* __restrict__ inputs) {
    int b = blockIdx.x;
    int tid = threadIdx.x;                 // 256 threads
    __shared__ float sA[Nn * Nn];
    __shared__ __align__(16) float sH[Nn * Hh];
    const float* Ab = Amat + (size_t)b * Nn * 2 * Nn;

#pragma unroll
    for (int pass = 0; pass < 2; pass++) {
        const float* bias = pass ? b_oah : b_iah;
        int acol = pass ? Nn : 0;
        for (int i = tid; i < Nn * Nn; i += 256)
            sA[i] = Ab[(i / Nn) * (2 * Nn) + acol + (i % Nn)];
        for (int i = tid; i < Nn * (Hh / 4); i += 256) {
            int k = i >> 5, q = i & 31;
            ((float4*)sH)[i] =
                ((const float4*)cat)[((size_t)b * Nn + k) * 160 + pass * 32 + q];
        }
        __syncthreads();
        for (int o = tid; o < 25 * 32; o += 256) {
            int n = o >> 5, q = o & 31;
            float4 bq = *(const float4*)(bias + q * 4);
            float4 a0 = bq, a1 = bq;
#pragma unroll 10
            for (int k = 0; k < Nn; k++) {
                float4 hv = *(const float4*)&sH[k * Hh + q * 4];
                float w0 = sA[n * Nn + k];
                float w1 = sA[(n + 25) * Nn + k];
                a0.x += w0 * hv.x; a0.y += w0 * hv.y;
                a0.z += w0 * hv.z; a0.w += w0 * hv.w;
                a1.x += w1 * hv.x; a1.y += w1 * hv.y;
                a1.z += w1 * hv.z; a1.w += w1 * hv.w;
            }
            a0.x = roundtf(a0.x); a0.y = roundtf(a0.y);
            a0.z = roundtf(a0.z); a0.w = roundtf(a0.w);
            a1.x = roundtf(a1.x); a1.y = roundtf(a1.y);
            a1.z = roundtf(a1.z); a1.w = roundtf(a1.w);
            *(float4*)(inputs + ((size_t)b * Nn + n) * (2 * Hh) + pass * Hh + q * 4) = a0;
            *(float4*)(inputs + ((size_t)b * Nn + n + 25) * (2 * Hh) + pass * Hh + q * 4) = a1;
        }
        __syncthreads();
    }
}

// ---------------- GRU gate math (float4 vectorized) --------------------------
__global__ void gru_kernel(const float4* __restrict__ gi,
                           const float4* __restrict__ cat,
                           const float4* __restrict__ h,
                           float4* __restrict__ newh, int total4) {
    int i = blockIdx.x * blockDim.x + threadIdx.x;
    if (i >= total4) return;
    int bn = i >> 5, qq = i & 31;          // Hh/4 = 32 float4 per row
    size_t gibase = (size_t)bn * 96;       // 3*Hh/4
    size_t cbase  = (size_t)bn * 160;      // 640/4
    float4 ir = gi[gibase + qq];
    float4 ii = gi[gibase + 32 + qq];
    float4 in_ = gi[gibase + 64 + qq];
    float4 hr = cat[cbase + 64 + qq];
    float4 hi = cat[cbase + 96 + qq];
    float4 hn = cat[cbase + 128 + qq];
    float4 hv = h[i];
    float4 o;
#define GRU1(comp) { \
        float r = 1.f / (1.f + expf(-(ir.comp + hr.comp))); \
        float z = 1.f / (1.f + expf(-(ii.comp + hi.comp))); \
        float ng = tanhf(in_.comp + r * hn.comp); \
        o.comp = roundtf(ng + z * (hv.comp - ng)); }
    GRU1(x) GRU1(y) GRU1(z) GRU1(w)
#undef GRU1
    newh[i] = o;
}

// ---------------- ht only ----------------------------------------------------
__global__ void ht_kernel(const int* __restrict__ alias,
                          const int* __restrict__ mask,
                          const float* __restrict__ newh,
                          float* __restrict__ ht) {
    int b = blockIdx.x;
    int lane = threadIdx.x;                // 32 threads
    int c = 0;
    if (lane < Ss)      c += mask[b * Ss + lane];
    if (lane + 32 < Ss) c += mask[b * Ss + lane + 32];
#pragma unroll
    for (int off = 16; off; off >>= 1)
        c += __shfl_down_sync(0xffffffffu, c, off);
    c = __shfl_sync(0xffffffffu, c, 0);
    int node = alias[b * Ss + (c - 1)];
    const float4* hrow = (const float4*)newh + ((size_t)b * Nn + node) * (Hh / 4);
    ((float4*)ht)[(size_t)b * (Hh / 4) + lane] = hrow[lane];
}

// ---------------- attention readout ------------------------------------------
__global__ void attn_kernel(const float* __restrict__ q1,
                            const float* __restrict__ nq,
                            const float* __restrict__ fc3_w,
                            const float* __restrict__ newh,
                            const int* __restrict__ alias,
                            const int* __restrict__ mask,
                            float* __restrict__ avec) {
    int b = blockIdx.x;
    int tid = threadIdx.x;                 // 128
    int warp = tid >> 5, lane = tid & 31;
    __shared__ float salpha[Ss];
    __shared__ int sal[Ss];
    if (tid < Ss) sal[tid] = alias[b * Ss + tid];
    __syncthreads();
    for (int s = warp; s < Ss; s += 4) {
        size_t rowbase = ((size_t)b * Nn + sal[s]) * Hh;
        float part = 0.f;
        for (int hh = lane; hh < Hh; hh += 32) {
            float v = q1[(size_t)b * Hh + hh] + nq[rowbase + hh];
            part += fc3_w[hh] / (1.f + expf(-v));
        }
#pragma unroll
        for (int off = 16; off; off >>= 1)
            part += __shfl_down_sync(0xffffffffu, part, off);
        if (lane == 0) salpha[s] = part;
    }
    __syncthreads();
    int hh = tid;
    float acc = 0.f;
    for (int s = 0; s < Ss; s++) {
        float m = (float)mask[b * Ss + s];
        acc += salpha[s] * newh[((size_t)b * Nn + sal[s]) * Hh + hh] * m;
    }
    avec[(size_t)b * Hh + hh] = roundtf(acc);
}

// ---------------- launch -----------------------------------------------------
extern "C" void kernel_launch(void* const* d_in, const int* in_sizes, int n_in,
                              void* d_out, int out_size) {
    const int*   alias_inputs = (const int*)  d_in[0];
    const float* A            = (const float*)d_in[1];
    const int*   items        = (const int*)  d_in[2];
    const int*   mask         = (const int*)  d_in[3];
    const float* emb          = (const float*)d_in[4];
    const float* ein_w        = (const float*)d_in[5];
    const float* ein_b        = (const float*)d_in[6];
    const float* eou_w        = (const float*)d_in[7];
    const float* eou_b        = (const float*)d_in[8];
    const float* w_ih         = (const float*)d_in[9];
    const float* w_hh         = (const float*)d_in[10];
    const float* b_ih         = (const float*)d_in[11];
    const float* b_hh         = (const float*)d_in[12];
    const float* b_iah        = (const float*)d_in[13];
    const float* b_oah        = (const float*)d_in[14];
    const float* fc1_w        = (const float*)d_in[15];
    const float* fc1_b        = (const float*)d_in[16];
    const float* fc2_w        = (const float*)d_in[17];
    const float* fc2_b        = (const float*)d_in[18];
    const float* fc3_w        = (const float*)d_in[19];
    float* out = (float*)d_out;

    const int SM = 6 * GBUF;               // 110592 B (3-stage, A+B)
    cudaFuncSetAttribute(gemm2_kernel<false>,
                         cudaFuncAttributeMaxDynamicSharedMemorySize, SM);
    cudaFuncSetAttribute(gemm2_kernel<true>,
                         cudaFuncAttributeMaxDynamicSharedMemorySize, SM);

    float *p_h, *p_cat, *p_inputs, *p_gi, *p_newh;
    float *p_ht, *p_q1, *p_nq, *p_avec, *p_wr, *p_bcat;
    cudaGetSymbolAddress((void**)&p_h,      g_h);
    cudaGetSymbolAddress((void**)&p_cat,    g_cat);
    cudaGetSymbolAddress((void**)&p_inputs, g_inputs);
    cudaGetSymbolAddress((void**)&p_gi,     g_gi);
    cudaGetSymbolAddress((void**)&p_newh,   g_newh);
    cudaGetSymbolAddress((void**)&p_ht,     g_ht);
    cudaGetSymbolAddress((void**)&p_q1,     g_q1);
    cudaGetSymbolAddress((void**)&p_nq,     g_nq);
    cudaGetSymbolAddress((void**)&p_avec,   g_avec);
    cudaGetSymbolAddress((void**)&p_wr,     g_wr);
    cudaGetSymbolAddress((void**)&p_bcat,   g_bcat);

    const int BN = Bb * Nn;                // 51200 = 400 * 128

    // 0. prep
    pack_cat_kernel<<<(640 * 32 + 255) / 256, 256>>>(
        ein_w, eou_w, w_hh, ein_b, eou_b, b_hh, p_wr + WR_CAT, p_bcat);
    round_all_kernel<<<(32768 + 255) / 256, 256>>>(w_ih, fc1_w, fc2_w, p_wr);
    // 1. gather (rounds inline from raw emb)
    {
        int total4 = BN * (Hh / 4);
        gather_kernel<<<(total4 + 255) / 256, 256>>>(items, emb, p_h, total4);
    }
    // 2. cat GEMM: [hin|hout|gh] = h @ [ein;eou;whh]^T  (M=51200, N=640, K=128)
    gemm2_kernel<false><<<dim3(5, BN / 128), 128, SM>>>(p_h, p_wr + WR_CAT,
                                                        p_bcat, p_cat, BN, 640, Hh);
    // 3. adjacency matmuls
    amm_kernel<<<Bb, 256>>>(A, p_cat, b_iah, b_oah, p_inputs);
    // 4. gi  (N=384, K=256)
    gemm2_kernel<false><<<dim3(3, BN / 128), 128, SM>>>(p_inputs, p_wr + WR_WIH,
                                                        b_ih, p_gi, BN, 3 * Hh, 2 * Hh);
    // 5. GRU (float4)
    {
        int total4 = BN * (Hh / 4);
        gru_kernel<<<(total4 + 255) / 256, 256>>>((const float4*)p_gi,
                                                  (const float4*)p_cat,
                                                  (const float4*)p_h,
                                                  (float4*)p_newh, total4);
    }
    // 6. ht
    ht_kernel<<<Bb, 32>>>(alias_inputs, mask, p_newh, p_ht);
    // 7. q1 (M=1024, N=128, K=128)
    gemm2_kernel<false><<<dim3(1, Bb / 128), 128, SM>>>(p_ht, p_wr + WR_FC1,
                                                        fc1_b, p_q1, Bb, Hh, Hh);
    // 8. nq = newh @ fc2^T (+fc2_b)  (M=51200, N=128, K=128)
    gemm2_kernel<false><<<dim3(1, BN / 128), 128, SM>>>(p_newh, p_wr + WR_FC2,
                                                        fc2_b, p_nq, BN, Hh, Hh);
    // 9. attention
    attn_kernel<<<Bb, 128>>>(p_q1, p_nq, fc3_w, p_newh, alias_inputs, mask, p_avec);
    // 10. scoring: out = avec @ emb[1:].T  (raw emb, in-loop rna cvt on B)
    gemm2_kernel<true><<<dim3((V1 + 127) / 128, Bb / 128), 128, SM>>>(
        p_avec, emb + Hh, nullptr, out, Bb, V1, Hh);
    (void)in_sizes; (void)n_in; (void)out_size;
}

// round 13
// speedup vs baseline: 1.2657x; 1.0182x over previous
#include <cuda_runtime.h>
#include <cuda_bf16.h>
#include <cstdint>

// SR-GNN forward. Shapes fixed: B=1024, N=50, S=50, H=128, V=100000
#define Bb 1024
#define Nn 50
#define Ss 50
#define Hh 128
#define Vv 100000
#define V1 (Vv - 1)

// ---------------- scratch ---------------------------------------------------
__device__ float g_h     [Bb * Nn * Hh];
__device__ float g_cat   [Bb * Nn * 640];     // [hin(128) | hout(128) | gh(384)]
__device__ float g_inputs[Bb * Nn * 2 * Hh];
__device__ float g_gi    [Bb * Nn * 3 * Hh];
__device__ float g_newh  [Bb * Nn * Hh];
__device__ float g_ht    [Bb * Hh];
__device__ float g_q1    [Bb * Hh];
__device__ float g_nq    [Bb * Nn * Hh];
__device__ float g_avec  [Bb * Hh];
__device__ float g_wr    [212992];            // packed tf32-rounded weights
__device__ float g_bcat  [640];               // packed bias for cat GEMM

// packed weight offsets (floats)
#define WR_CAT 0                  // 640x128 = 81920
#define WR_WIH 81920              // 384x256 = 98304
#define WR_FC1 180224             // 128x128 = 16384
#define WR_FC2 196608             // 128x128 = 16384

// ---------------- tf32 helpers ----------------------------------------------
__device__ __forceinline__ uint32_t f2tf32(float x) {
    uint32_t r;
    asm("cvt.rna.tf32.f32 %0, %1;" : "=r"(r) : "f"(x));
    return r;
}
__device__ __forceinline__ uint32_t u2tf32(uint32_t x) {
    uint32_t r;
    asm("cvt.rna.tf32.f32 %0, %1;" : "=r"(r) : "r"(x));
    return r;
}
__device__ __forceinline__ float roundtf(float x) {
    return __uint_as_float(f2tf32(x));
}
__device__ __forceinline__ void mma_tf32(float* c, const uint32_t* a,
                                         const uint32_t* b) {
    asm volatile(
        "mma.sync.aligned.m16n8k8.row.col.f32.tf32.tf32.f32 "
        "{%0,%1,%2,%3}, {%4,%5,%6,%7}, {%8,%9}, {%0,%1,%2,%3};"
        : "+f"(c[0]), "+f"(c[1]), "+f"(c[2]), "+f"(c[3])
        : "r"(a[0]), "r"(a[1]), "r"(a[2]), "r"(a[3]), "r"(b[0]), "r"(b[1]));
}
__device__ __forceinline__ void ldmx4(uint32_t& r0, uint32_t& r1,
                                      uint32_t& r2, uint32_t& r3, uint32_t addr) {
    asm volatile("ldmatrix.sync.aligned.m8n8.x4.shared.b16 {%0,%1,%2,%3}, [%4];"
                 : "=r"(r0), "=r"(r1), "=r"(r2), "=r"(r3) : "r"(addr));
}
__device__ __forceinline__ void cp16(uint32_t dst, const void* src, bool pred) {
    int sz = pred ? 16 : 0;
    asm volatile("cp.async.cg.shared.global [%0], [%1], 16, %2;\n"
                 :: "r"(dst), "l"(src), "r"(sz));
}

// ---------------- prep kernels ----------------------------------------------
__global__ void round_all_kernel(const float* __restrict__ w_ih,
                                 const float* __restrict__ fc1_w,
                                 const float* __restrict__ fc2_w,
                                 float* __restrict__ wr) {
    int i = blockIdx.x * blockDim.x + threadIdx.x;   // 32768 float4s
    if (i >= 32768) return;
    const float4* src;
    float4* dst;
    if (i < 24576)      { src = (const float4*)w_ih + i;
                          dst = (float4*)(wr + WR_WIH) + i; }
    else if (i < 28672) { src = (const float4*)fc1_w + (i - 24576);
                          dst = (float4*)(wr + WR_FC1) + (i - 24576); }
    else                { src = (const float4*)fc2_w + (i - 28672);
                          dst = (float4*)(wr + WR_FC2) + (i - 28672); }
    float4 v = *src;
    *dst = make_float4(roundtf(v.x), roundtf(v.y), roundtf(v.z), roundtf(v.w));
}

__global__ void pack_cat_kernel(const float* __restrict__ ein_w,
                                const float* __restrict__ eou_w,
                                const float* __restrict__ w_hh,
                                const float* __restrict__ ein_b,
                                const float* __restrict__ eou_b,
                                const float* __restrict__ b_hh,
                                float* __restrict__ wcat,
                                float* __restrict__ bcat) {
    int i = blockIdx.x * blockDim.x + threadIdx.x;   // 640*32 float4s
    if (i < 640 * 32) {
        int r = i >> 5, q = i & 31;
        const float* src = (r < 128) ? (ein_w + (size_t)r * Hh)
                         : (r < 256) ? (eou_w + (size_t)(r - 128) * Hh)
                                     : (w_hh + (size_t)(r - 256) * Hh);
        float4 v = ((const float4*)src)[q];
        ((float4*)wcat)[i] = make_float4(roundtf(v.x), roundtf(v.y),
                                         roundtf(v.z), roundtf(v.w));
    }
    if (i < 640) {
        bcat[i] = (i < 128) ? ein_b[i]
                : (i < 256) ? eou_b[i - 128]
                            : b_hh[i - 256];
    }
}

// ---------------- HMMA tf32 GEMM (ldmatrix fragments, 2-stage) ---------------
// C[M,N] = A[M,K] @ W[N,K]^T (+bias).
// CVTB=false: W pre-rounded tf32. CVTB=true: W raw fp32, rna-cvt on B frags.
// CTA 128x128, 128 threads = 4 warps (2x2 of 64x64), BK=32.
// smem row stride 176B (44 u32): 16B-aligned rows, conflict-free ldmatrix.
#define TILEB 22528                       // 128 rows * 176 B
#define ROWB  176
template <bool CVTB>
__global__ void __launch_bounds__(128, 2)
gemm2_kernel(const float* __restrict__ A, const float* __restrict__ W,
             const float* __restrict__ bias, float* __restrict__ C,
             int M, int N, int K) {
    extern __shared__ char dsm[];
    const uint32_t sbase = (uint32_t)__cvta_generic_to_shared(dsm);
    const int tid  = threadIdx.x;
    const int warp = tid >> 5, lane = tid & 31;
    const int g  = lane >> 2;
    const int tg = lane & 3;
    const int wm = (warp & 1) * 64;
    const int wn = (warp >> 1) * 64;
    const int m0 = blockIdx.y * 128;
    const int n0 = blockIdx.x * 128;

    // ldmatrix per-thread address components
    const int lrow = lane & 7, lmi = lane >> 3;
    const uint32_t aoff = (uint32_t)((lrow + (lmi & 1) * 8) * ROWB + (lmi >> 1) * 16);
    const uint32_t boff = (uint32_t)((lrow + (lmi >> 1) * 8) * ROWB + (lmi & 1) * 16);

    float acc[4][8][4];
#pragma unroll
    for (int mt = 0; mt < 4; mt++)
#pragma unroll
        for (int nt = 0; nt < 8; nt++)
#pragma unroll
            for (int i = 0; i < 4; i++) acc[mt][nt][i] = 0.f;

    const int nch = K >> 5;

    auto stage = [&](int c, int s) {
        const int kt = c * 32;
        uint32_t aB = sbase + s * TILEB;
        uint32_t bB = sbase + 2 * TILEB + s * TILEB;
#pragma unroll
        for (int i = 0; i < 8; i++) {
            int id2 = tid + i * 128;           // 1024 16B chunks per tile
            int row = id2 >> 3, q = id2 & 7;
            bool pa = (m0 + row) < M;
            const float* sa = pa ? (A + (size_t)(m0 + row) * K + kt + q * 4) : A;
            cp16(aB + row * ROWB + q * 16, sa, pa);
            bool pb = (n0 + row) < N;
            const float* sb = pb ? (W + (size_t)(n0 + row) * K + kt + q * 4) : W;
            cp16(bB + row * ROWB + q * 16, sb, pb);
        }
        asm volatile("cp.async.commit_group;\n" ::: "memory");
    };

    stage(0, 0);
    for (int c = 0; c < nch; c++) {
        if (c + 1 < nch) {
            stage(c + 1, (c + 1) & 1);
            asm volatile("cp.async.wait_group 1;" ::: "memory");
        } else {
            asm volatile("cp.async.wait_group 0;" ::: "memory");
        }
        __syncthreads();

        const uint32_t aB = sbase + (c & 1) * TILEB + wm * ROWB + aoff;
        const uint32_t bB = sbase + 2 * TILEB + (c & 1) * TILEB + wn * ROWB + boff;

#pragma unroll
        for (int ks = 0; ks < 4; ks++) {
            const uint32_t kb = ks * 32;       // 8 u32 = 32 bytes
            uint32_t af[4][4], bf[8][2];
#pragma unroll
            for (int mt = 0; mt < 4; mt++)
                ldmx4(af[mt][0], af[mt][1], af[mt][2], af[mt][3],
                      aB + mt * (16 * ROWB) + kb);
#pragma unroll
            for (int np = 0; np < 4; np++) {
                ldmx4(bf[2 * np][0], bf[2 * np][1],
                      bf[2 * np + 1][0], bf[2 * np + 1][1],
                      bB + np * (16 * ROWB) + kb);
                if (CVTB) {
                    bf[2 * np][0]     = u2tf32(bf[2 * np][0]);
                    bf[2 * np][1]     = u2tf32(bf[2 * np][1]);
                    bf[2 * np + 1][0] = u2tf32(bf[2 * np + 1][0]);
                    bf[2 * np + 1][1] = u2tf32(bf[2 * np + 1][1]);
                }
            }
#pragma unroll
            for (int mt = 0; mt < 4; mt++)
#pragma unroll
                for (int nt = 0; nt < 8; nt++)
                    mma_tf32(acc[mt][nt], af[mt], bf[nt]);
        }
        __syncthreads();
    }

    const bool n_even_full = ((N & 1) == 0);
#pragma unroll
    for (int mt = 0; mt < 4; mt++) {
        int row = m0 + wm + mt * 16 + g;
#pragma unroll
        for (int nt = 0; nt < 8; nt++) {
            int col = n0 + wn + nt * 8 + tg * 2;
            const float* c0 = &acc[mt][nt][0];
            if (n_even_full && col + 1 < N) {
                float b0 = bias ? __ldg(bias + col) : 0.f;
                float b1 = bias ? __ldg(bias + col + 1) : 0.f;
                *(float2*)(C + (size_t)row * N + col) =
                    make_float2(c0[0] + b0, c0[1] + b1);
                *(float2*)(C + (size_t)(row + 8) * N + col) =
                    make_float2(c0[2] + b0, c0[3] + b1);
            } else {
                if (col < N) {
                    float b0 = bias ? __ldg(bias + col) : 0.f;
                    C[(size_t)row * N + col]       = c0[0] + b0;
                    C[(size_t)(row + 8) * N + col] = c0[2] + b0;
                }
                if (col + 1 < N) {
                    float b1 = bias ? __ldg(bias + col + 1) : 0.f;
                    C[(size_t)row * N + col + 1]       = c0[1] + b1;
                    C[(size_t)(row + 8) * N + col + 1] = c0[3] + b1;
                }
            }
        }
    }
}

// ---------------- h = round(emb[items]) --------------------------------------
__global__ void gather_kernel(const int* __restrict__ items,
                              const float* __restrict__ emb,
                              float* __restrict__ h, int total4) {
    int i = blockIdx.x * blockDim.x + threadIdx.x;
    if (i >= total4) return;
    int bn = i >> 5, q = i & 31;
    int it = items[bn];
    float4 v = ((const float4*)emb)[(size_t)it * 32 + q];
    ((float4*)h)[i] = make_float4(roundtf(v.x), roundtf(v.y),
                                  roundtf(v.z), roundtf(v.w));
}

// ---------------- batched adjacency matmul -----------------------------------
__global__ void amm_kernel(const float* __restrict__ Amat,
                           const float* __restrict__ cat,
                           const float* __restrict__ b_iah,
                           const float* __restrict__ b_oah,
                           float* __restrict__ inputs) {
    int b = blockIdx.x;
    int tid = threadIdx.x;                 // 256 threads
    __shared__ float sA[Nn * Nn];
    __shared__ __align__(16) float sH[Nn * Hh];
    const float* Ab = Amat + (size_t)b * Nn * 2 * Nn;

#pragma unroll
    for (int pass = 0; pass < 2; pass++) {
        const float* bias = pass ? b_oah : b_iah;
        int acol = pass ? Nn : 0;
        for (int i = tid; i < Nn * Nn; i += 256)
            sA[i] = Ab[(i / Nn) * (2 * Nn) + acol + (i % Nn)];
        for (int i = tid; i < Nn * (Hh / 4); i += 256) {
            int k = i >> 5, q = i & 31;
            ((float4*)sH)[i] =
                ((const float4*)cat)[((size_t)b * Nn + k) * 160 + pass * 32 + q];
        }
        __syncthreads();
        for (int o = tid; o < 25 * 32; o += 256) {
            int n = o >> 5, q = o & 31;
            float4 bq = *(const float4*)(bias + q * 4);
            float4 a0 = bq, a1 = bq;
#pragma unroll 10
            for (int k = 0; k < Nn; k++) {
                float4 hv = *(const float4*)&sH[k * Hh + q * 4];
                float w0 = sA[n * Nn + k];
                float w1 = sA[(n + 25) * Nn + k];
                a0.x += w0 * hv.x; a0.y += w0 * hv.y;
                a0.z += w0 * hv.z; a0.w += w0 * hv.w;
                a1.x += w1 * hv.x; a1.y += w1 * hv.y;
                a1.z += w1 * hv.z; a1.w += w1 * hv.w;
            }
            a0.x = roundtf(a0.x); a0.y = roundtf(a0.y);
            a0.z = roundtf(a0.z); a0.w = roundtf(a0.w);
            a1.x = roundtf(a1.x); a1.y = roundtf(a1.y);
            a1.z = roundtf(a1.z); a1.w = roundtf(a1.w);
            *(float4*)(inputs + ((size_t)b * Nn + n) * (2 * Hh) + pass * Hh + q * 4) = a0;
            *(float4*)(inputs + ((size_t)b * Nn + n + 25) * (2 * Hh) + pass * Hh + q * 4) = a1;
        }
        __syncthreads();
    }
}

// ---------------- GRU gate math (float4 vectorized) --------------------------
__global__ void gru_kernel(const float4* __restrict__ gi,
                           const float4* __restrict__ cat,
                           const float4* __restrict__ h,
                           float4* __restrict__ newh, int total4) {
    int i = blockIdx.x * blockDim.x + threadIdx.x;
    if (i >= total4) return;
    int bn = i >> 5, qq = i & 31;
    size_t gibase = (size_t)bn * 96;
    size_t cbase  = (size_t)bn * 160;
    float4 ir = gi[gibase + qq];
    float4 ii = gi[gibase + 32 + qq];
    float4 in_ = gi[gibase + 64 + qq];
    float4 hr = cat[cbase + 64 + qq];
    float4 hi = cat[cbase + 96 + qq];
    float4 hn = cat[cbase + 128 + qq];
    float4 hv = h[i];
    float4 o;
#define GRU1(comp) { \
        float r = 1.f / (1.f + expf(-(ir.comp + hr.comp))); \
        float z = 1.f / (1.f + expf(-(ii.comp + hi.comp))); \
        float ng = tanhf(in_.comp + r * hn.comp); \
        o.comp = roundtf(ng + z * (hv.comp - ng)); }
    GRU1(x) GRU1(y) GRU1(z) GRU1(w)
#undef GRU1
    newh[i] = o;
}

// ---------------- ht only ----------------------------------------------------
__global__ void ht_kernel(const int* __restrict__ alias,
                          const int* __restrict__ mask,
                          const float* __restrict__ newh,
                          float* __restrict__ ht) {
    int b = blockIdx.x;
    int lane = threadIdx.x;                // 32 threads
    int c = 0;
    if (lane < Ss)      c += mask[b * Ss + lane];
    if (lane + 32 < Ss) c += mask[b * Ss + lane + 32];
#pragma unroll
    for (int off = 16; off; off >>= 1)
        c += __shfl_down_sync(0xffffffffu, c, off);
    c = __shfl_sync(0xffffffffu, c, 0);
    int node = alias[b * Ss + (c - 1)];
    const float4* hrow = (const float4*)newh + ((size_t)b * Nn + node) * (Hh / 4);
    ((float4*)ht)[(size_t)b * (Hh / 4) + lane] = hrow[lane];
}

// ---------------- attention readout ------------------------------------------
__global__ void attn_kernel(const float* __restrict__ q1,
                            const float* __restrict__ nq,
                            const float* __restrict__ fc3_w,
                            const float* __restrict__ newh,
                            const int* __restrict__ alias,
                            const int* __restrict__ mask,
                            float* __restrict__ avec) {
    int b = blockIdx.x;
    int tid = threadIdx.x;                 // 128
    int warp = tid >> 5, lane = tid & 31;
    __shared__ float salpha[Ss];
    __shared__ int sal[Ss];
    if (tid < Ss) sal[tid] = alias[b * Ss + tid];
    __syncthreads();
    for (int s = warp; s < Ss; s += 4) {
        size_t rowbase = ((size_t)b * Nn + sal[s]) * Hh;
        float part = 0.f;
        for (int hh = lane; hh < Hh; hh += 32) {
            float v = q1[(size_t)b * Hh + hh] + nq[rowbase + hh];
            part += fc3_w[hh] / (1.f + expf(-v));
        }
#pragma unroll
        for (int off = 16; off; off >>= 1)
            part += __shfl_down_sync(0xffffffffu, part, off);
        if (lane == 0) salpha[s] = part;
    }
    __syncthreads();
    int hh = tid;
    float acc = 0.f;
    for (int s = 0; s < Ss; s++) {
        float m = (float)mask[b * Ss + s];
        acc += salpha[s] * newh[((size_t)b * Nn + sal[s]) * Hh + hh] * m;
    }
    avec[(size_t)b * Hh + hh] = roundtf(acc);
}

// ---------------- launch -----------------------------------------------------
extern "C" void kernel_launch(void* const* d_in, const int* in_sizes, int n_in,
                              void* d_out, int out_size) {
    const int*   alias_inputs = (const int*)  d_in[0];
    const float* A            = (const float*)d_in[1];
    const int*   items        = (const int*)  d_in[2];
    const int*   mask         = (const int*)  d_in[3];
    const float* emb          = (const float*)d_in[4];
    const float* ein_w        = (const float*)d_in[5];
    const float* ein_b        = (const float*)d_in[6];
    const float* eou_w        = (const float*)d_in[7];
    const float* eou_b        = (const float*)d_in[8];
    const float* w_ih         = (const float*)d_in[9];
    const float* w_hh         = (const float*)d_in[10];
    const float* b_ih         = (const float*)d_in[11];
    const float* b_hh         = (const float*)d_in[12];
    const float* b_iah        = (const float*)d_in[13];
    const float* b_oah        = (const float*)d_in[14];
    const float* fc1_w        = (const float*)d_in[15];
    const float* fc1_b        = (const float*)d_in[16];
    const float* fc2_w        = (const float*)d_in[17];
    const float* fc2_b        = (const float*)d_in[18];
    const float* fc3_w        = (const float*)d_in[19];
    float* out = (float*)d_out;

    const int SM = 4 * TILEB;              // 90112 B (2-stage, A+B)
    cudaFuncSetAttribute(gemm2_kernel<false>,
                         cudaFuncAttributeMaxDynamicSharedMemorySize, SM);
    cudaFuncSetAttribute(gemm2_kernel<true>,
                         cudaFuncAttributeMaxDynamicSharedMemorySize, SM);

    float *p_h, *p_cat, *p_inputs, *p_gi, *p_newh;
    float *p_ht, *p_q1, *p_nq, *p_avec, *p_wr, *p_bcat;
    cudaGetSymbolAddress((void**)&p_h,      g_h);
    cudaGetSymbolAddress((void**)&p_cat,    g_cat);
    cudaGetSymbolAddress((void**)&p_inputs, g_inputs);
    cudaGetSymbolAddress((void**)&p_gi,     g_gi);
    cudaGetSymbolAddress((void**)&p_newh,   g_newh);
    cudaGetSymbolAddress((void**)&p_ht,     g_ht);
    cudaGetSymbolAddress((void**)&p_q1,     g_q1);
    cudaGetSymbolAddress((void**)&p_nq,     g_nq);
    cudaGetSymbolAddress((void**)&p_avec,   g_avec);
    cudaGetSymbolAddress((void**)&p_wr,     g_wr);
    cudaGetSymbolAddress((void**)&p_bcat,   g_bcat);

    const int BN = Bb * Nn;                // 51200 = 400 * 128

    // 0. prep
    pack_cat_kernel<<<(640 * 32 + 255) / 256, 256>>>(
        ein_w, eou_w, w_hh, ein_b, eou_b, b_hh, p_wr + WR_CAT, p_bcat);
    round_all_kernel<<<(32768 + 255) / 256, 256>>>(w_ih, fc1_w, fc2_w, p_wr);
    // 1. gather (rounds inline from raw emb)
    {
        int total4 = BN * (Hh / 4);
        gather_kernel<<<(total4 + 255) / 256, 256>>>(items, emb, p_h, total4);
    }
    // 2. cat GEMM: [hin|hout|gh] = h @ [ein;eou;whh]^T  (M=51200, N=640, K=128)
    gemm2_kernel<false><<<dim3(5, BN / 128), 128, SM>>>(p_h, p_wr + WR_CAT,
                                                        p_bcat, p_cat, BN, 640, Hh);
    // 3. adjacency matmuls
    amm_kernel<<<Bb, 256>>>(A, p_cat, b_iah, b_oah, p_inputs);
    // 4. gi  (N=384, K=256)
    gemm2_kernel<false><<<dim3(3, BN / 128), 128, SM>>>(p_inputs, p_wr + WR_WIH,
                                                        b_ih, p_gi, BN, 3 * Hh, 2 * Hh);
    // 5. GRU (float4)
    {
        int total4 = BN * (Hh / 4);
        gru_kernel<<<(total4 + 255) / 256, 256>>>((const float4*)p_gi,
                                                  (const float4*)p_cat,
                                                  (const float4*)p_h,
                                                  (float4*)p_newh, total4);
    }
    // 6. ht
    ht_kernel<<<Bb, 32>>>(alias_inputs, mask, p_newh, p_ht);
    // 7. q1 (M=1024, N=128, K=128)
    gemm2_kernel<false><<<dim3(1, Bb / 128), 128, SM>>>(p_ht, p_wr + WR_FC1,
                                                        fc1_b, p_q1, Bb, Hh, Hh);
    // 8. nq = newh @ fc2^T (+fc2_b)  (M=51200, N=128, K=128)
    gemm2_kernel<false><<<dim3(1, BN / 128), 128, SM>>>(p_newh, p_wr + WR_FC2,
                                                        fc2_b, p_nq, BN, Hh, Hh);
    // 9. attention
    attn_kernel<<<Bb, 128>>>(p_q1, p_nq, fc3_w, p_newh, alias_inputs, mask, p_avec);
    // 10. scoring: out = avec @ emb[1:].T  (raw emb, in-loop rna cvt on B)
    gemm2_kernel<true><<<dim3((V1 + 127) / 128, Bb / 128), 128, SM>>>(
        p_avec, emb + Hh, nullptr, out, Bb, V1, Hh);
    (void)in_sizes; (void)n_in; (void)out_size;
}

// round 14
// speedup vs baseline: 1.3313x; 1.0518x over previous
#include <cuda_runtime.h>
#include <cuda_bf16.h>
#include <cstdint>

// SR-GNN forward. Shapes fixed: B=1024, N=50, S=50, H=128, V=100000
#define Bb 1024
#define Nn 50
#define Ss 50
#define Hh 128
#define Vv 100000
#define V1 (Vv - 1)

// ---------------- scratch ---------------------------------------------------
__device__ float g_h     [Bb * Nn * Hh];
__device__ float g_cat   [Bb * Nn * 640];     // [hin(128) | hout(128) | gh(384)]
__device__ float g_inputs[Bb * Nn * 2 * Hh];
__device__ float g_gi    [Bb * Nn * 3 * Hh];
__device__ float g_newh  [Bb * Nn * Hh];
__device__ float g_ht    [Bb * Hh];
__device__ float g_q1    [Bb * Hh];
__device__ float g_nq    [Bb * Nn * Hh];
__device__ float g_avec  [Bb * Hh];
__device__ float g_wr    [212992];            // packed tf32-rounded weights
__device__ float g_bcat  [640];               // packed bias for cat GEMM

// packed weight offsets (floats)
#define WR_CAT 0                  // 640x128 = 81920
#define WR_WIH 81920              // 384x256 = 98304
#define WR_FC1 180224             // 128x128 = 16384
#define WR_FC2 196608             // 128x128 = 16384

// ---------------- tf32 helpers ----------------------------------------------
__device__ __forceinline__ uint32_t f2tf32(float x) {
    uint32_t r;
    asm("cvt.rna.tf32.f32 %0, %1;" : "=r"(r) : "f"(x));
    return r;
}
__device__ __forceinline__ uint32_t u2tf32(uint32_t x) {
    uint32_t r;
    asm("cvt.rna.tf32.f32 %0, %1;" : "=r"(r) : "r"(x));
    return r;
}
__device__ __forceinline__ float roundtf(float x) {
    return __uint_as_float(f2tf32(x));
}
__device__ __forceinline__ void mma_tf32(float* c, const uint32_t* a,
                                         const uint32_t* b) {
    asm volatile(
        "mma.sync.aligned.m16n8k8.row.col.f32.tf32.tf32.f32 "
        "{%0,%1,%2,%3}, {%4,%5,%6,%7}, {%8,%9}, {%0,%1,%2,%3};"
        : "+f"(c[0]), "+f"(c[1]), "+f"(c[2]), "+f"(c[3])
        : "r"(a[0]), "r"(a[1]), "r"(a[2]), "r"(a[3]), "r"(b[0]), "r"(b[1]));
}
__device__ __forceinline__ void ldmx4(uint32_t& r0, uint32_t& r1,
                                      uint32_t& r2, uint32_t& r3, uint32_t addr) {
    asm volatile("ldmatrix.sync.aligned.m8n8.x4.shared.b16 {%0,%1,%2,%3}, [%4];"
                 : "=r"(r0), "=r"(r1), "=r"(r2), "=r"(r3) : "r"(addr));
}
__device__ __forceinline__ void cp16(uint32_t dst, const void* src, bool pred) {
    int sz = pred ? 16 : 0;
    asm volatile("cp.async.cg.shared.global [%0], [%1], 16, %2;\n"
                 :: "r"(dst), "l"(src), "r"(sz));
}

// ---------------- prep kernels ----------------------------------------------
__global__ void round_all_kernel(const float* __restrict__ w_ih,
                                 const float* __restrict__ fc1_w,
                                 const float* __restrict__ fc2_w,
                                 float* __restrict__ wr) {
    int i = blockIdx.x * blockDim.x + threadIdx.x;   // 32768 float4s
    if (i >= 32768) return;
    const float4* src;
    float4* dst;
    if (i < 24576)      { src = (const float4*)w_ih + i;
                          dst = (float4*)(wr + WR_WIH) + i; }
    else if (i < 28672) { src = (const float4*)fc1_w + (i - 24576);
                          dst = (float4*)(wr + WR_FC1) + (i - 24576); }
    else                { src = (const float4*)fc2_w + (i - 28672);
                          dst = (float4*)(wr + WR_FC2) + (i - 28672); }
    float4 v = *src;
    *dst = make_float4(roundtf(v.x), roundtf(v.y), roundtf(v.z), roundtf(v.w));
}

__global__ void pack_cat_kernel(const float* __restrict__ ein_w,
                                const float* __restrict__ eou_w,
                                const float* __restrict__ w_hh,
                                const float* __restrict__ ein_b,
                                const float* __restrict__ eou_b,
                                const float* __restrict__ b_hh,
                                float* __restrict__ wcat,
                                float* __restrict__ bcat) {
    int i = blockIdx.x * blockDim.x + threadIdx.x;   // 640*32 float4s
    if (i < 640 * 32) {
        int r = i >> 5, q = i & 31;
        const float* src = (r < 128) ? (ein_w + (size_t)r * Hh)
                         : (r < 256) ? (eou_w + (size_t)(r - 128) * Hh)
                                     : (w_hh + (size_t)(r - 256) * Hh);
        float4 v = ((const float4*)src)[q];
        ((float4*)wcat)[i] = make_float4(roundtf(v.x), roundtf(v.y),
                                         roundtf(v.z), roundtf(v.w));
    }
    if (i < 640) {
        bcat[i] = (i < 128) ? ein_b[i]
                : (i < 256) ? eou_b[i - 128]
                            : b_hh[i - 256];
    }
}

// ---------------- HMMA tf32 GEMM (ldmatrix, 8 warps, 2-stage) ----------------
// C[M,N] = A[M,K] @ W[N,K]^T (+bias).
// CVTB=false: W pre-rounded tf32. CVTB=true: W raw fp32, rna-cvt on B frags.
// CTA 128x128, 256 threads = 8 warps (2M x 4N), warp tile 64x32, BK=32.
// smem row stride 176B: 16B-aligned rows, conflict-free ldmatrix.
#define TILEB 22528                       // 128 rows * 176 B
#define ROWB  176
template <bool CVTB>
__global__ void __launch_bounds__(256, 2)
gemm2_kernel(const float* __restrict__ A, const float* __restrict__ W,
             const float* __restrict__ bias, float* __restrict__ C,
             int M, int N, int K) {
    extern __shared__ char dsm[];
    const uint32_t sbase = (uint32_t)__cvta_generic_to_shared(dsm);
    const int tid  = threadIdx.x;
    const int warp = tid >> 5, lane = tid & 31;
    const int g  = lane >> 2;
    const int tg = lane & 3;
    const int wm = (warp & 1) * 64;       // 2 warp rows
    const int wn = (warp >> 1) * 32;      // 4 warp cols
    const int m0 = blockIdx.y * 128;
    const int n0 = blockIdx.x * 128;

    // ldmatrix per-thread address components
    const int lrow = lane & 7, lmi = lane >> 3;
    const uint32_t aoff = (uint32_t)((lrow + (lmi & 1) * 8) * ROWB + (lmi >> 1) * 16);
    const uint32_t boff = (uint32_t)((lrow + (lmi >> 1) * 8) * ROWB + (lmi & 1) * 16);

    float acc[4][4][4];
#pragma unroll
    for (int mt = 0; mt < 4; mt++)
#pragma unroll
        for (int nt = 0; nt < 4; nt++)
#pragma unroll
            for (int i = 0; i < 4; i++) acc[mt][nt][i] = 0.f;

    const int nch = K >> 5;

    auto stage = [&](int c, int s) {
        const int kt = c * 32;
        uint32_t aB = sbase + s * TILEB;
        uint32_t bB = sbase + 2 * TILEB + s * TILEB;
#pragma unroll
        for (int i = 0; i < 4; i++) {
            int id2 = tid + i * 256;           // 1024 16B chunks per tile
            int row = id2 >> 3, q = id2 & 7;
            bool pa = (m0 + row) < M;
            const float* sa = pa ? (A + (size_t)(m0 + row) * K + kt + q * 4) : A;
            cp16(aB + row * ROWB + q * 16, sa, pa);
            bool pb = (n0 + row) < N;
            const float* sb = pb ? (W + (size_t)(n0 + row) * K + kt + q * 4) : W;
            cp16(bB + row * ROWB + q * 16, sb, pb);
        }
        asm volatile("cp.async.commit_group;\n" ::: "memory");
    };

    stage(0, 0);
    for (int c = 0; c < nch; c++) {
        if (c + 1 < nch) {
            stage(c + 1, (c + 1) & 1);
            asm volatile("cp.async.wait_group 1;" ::: "memory");
        } else {
            asm volatile("cp.async.wait_group 0;" ::: "memory");
        }
        __syncthreads();

        const uint32_t aB = sbase + (c & 1) * TILEB + wm * ROWB + aoff;
        const uint32_t bB = sbase + 2 * TILEB + (c & 1) * TILEB + wn * ROWB + boff;

#pragma unroll
        for (int ks = 0; ks < 4; ks++) {
            const uint32_t kb = ks * 32;       // 8 u32 = 32 bytes
            uint32_t af[4][4], bf[4][2];
#pragma unroll
            for (int mt = 0; mt < 4; mt++)
                ldmx4(af[mt][0], af[mt][1], af[mt][2], af[mt][3],
                      aB + mt * (16 * ROWB) + kb);
#pragma unroll
            for (int np = 0; np < 2; np++) {
                ldmx4(bf[2 * np][0], bf[2 * np][1],
                      bf[2 * np + 1][0], bf[2 * np + 1][1],
                      bB + np * (16 * ROWB) + kb);
                if (CVTB) {
                    bf[2 * np][0]     = u2tf32(bf[2 * np][0]);
                    bf[2 * np][1]     = u2tf32(bf[2 * np][1]);
                    bf[2 * np + 1][0] = u2tf32(bf[2 * np + 1][0]);
                    bf[2 * np + 1][1] = u2tf32(bf[2 * np + 1][1]);
                }
            }
#pragma unroll
            for (int mt = 0; mt < 4; mt++)
#pragma unroll
                for (int nt = 0; nt < 4; nt++)
                    mma_tf32(acc[mt][nt], af[mt], bf[nt]);
        }
        __syncthreads();
    }

    const bool n_even_full = ((N & 1) == 0);
#pragma unroll
    for (int mt = 0; mt < 4; mt++) {
        int row = m0 + wm + mt * 16 + g;
#pragma unroll
        for (int nt = 0; nt < 4; nt++) {
            int col = n0 + wn + nt * 8 + tg * 2;
            const float* c0 = &acc[mt][nt][0];
            if (n_even_full && col + 1 < N) {
                float b0 = bias ? __ldg(bias + col) : 0.f;
                float b1 = bias ? __ldg(bias + col + 1) : 0.f;
                *(float2*)(C + (size_t)row * N + col) =
                    make_float2(c0[0] + b0, c0[1] + b1);
                *(float2*)(C + (size_t)(row + 8) * N + col) =
                    make_float2(c0[2] + b0, c0[3] + b1);
            } else {
                if (col < N) {
                    float b0 = bias ? __ldg(bias + col) : 0.f;
                    C[(size_t)row * N + col]       = c0[0] + b0;
                    C[(size_t)(row + 8) * N + col] = c0[2] + b0;
                }
                if (col + 1 < N) {
                    float b1 = bias ? __ldg(bias + col + 1) : 0.f;
                    C[(size_t)row * N + col + 1]       = c0[1] + b1;
                    C[(size_t)(row + 8) * N + col + 1] = c0[3] + b1;
                }
            }
        }
    }
}

// ---------------- h = round(emb[items]) --------------------------------------
__global__ void gather_kernel(const int* __restrict__ items,
                              const float* __restrict__ emb,
                              float* __restrict__ h, int total4) {
    int i = blockIdx.x * blockDim.x + threadIdx.x;
    if (i >= total4) return;
    int bn = i >> 5, q = i & 31;
    int it = items[bn];
    float4 v = ((const float4*)emb)[(size_t)it * 32 + q];
    ((float4*)h)[i] = make_float4(roundtf(v.x), roundtf(v.y),
                                  roundtf(v.z), roundtf(v.w));
}

// ---------------- batched adjacency matmul -----------------------------------
__global__ void amm_kernel(const float* __restrict__ Amat,
                           const float* __restrict__ cat,
                           const float* __restrict__ b_iah,
                           const float* __restrict__ b_oah,
                           float* __restrict__ inputs) {
    int b = blockIdx.x;
    int tid = threadIdx.x;                 // 256 threads
    __shared__ float sA[Nn * Nn];
    __shared__ __align__(16) float sH[Nn * Hh];
    const float* Ab = Amat + (size_t)b * Nn * 2 * Nn;

#pragma unroll
    for (int pass = 0; pass < 2; pass++) {
        const float* bias = pass ? b_oah : b_iah;
        int acol = pass ? Nn : 0;
        for (int i = tid; i < Nn * Nn; i += 256)
            sA[i] = Ab[(i / Nn) * (2 * Nn) + acol + (i % Nn)];
        for (int i = tid; i < Nn * (Hh / 4); i += 256) {
            int k = i >> 5, q = i & 31;
            ((float4*)sH)[i] =
                ((const float4*)cat)[((size_t)b * Nn + k) * 160 + pass * 32 + q];
        }
        __syncthreads();
        for (int o = tid; o < 25 * 32; o += 256) {
            int n = o >> 5, q = o & 31;
            float4 bq = *(const float4*)(bias + q * 4);
            float4 a0 = bq, a1 = bq;
#pragma unroll 10
            for (int k = 0; k < Nn; k++) {
                float4 hv = *(const float4*)&sH[k * Hh + q * 4];
                float w0 = sA[n * Nn + k];
                float w1 = sA[(n + 25) * Nn + k];
                a0.x += w0 * hv.x; a0.y += w0 * hv.y;
                a0.z += w0 * hv.z; a0.w += w0 * hv.w;
                a1.x += w1 * hv.x; a1.y += w1 * hv.y;
                a1.z += w1 * hv.z; a1.w += w1 * hv.w;
            }
            a0.x = roundtf(a0.x); a0.y = roundtf(a0.y);
            a0.z = roundtf(a0.z); a0.w = roundtf(a0.w);
            a1.x = roundtf(a1.x); a1.y = roundtf(a1.y);
            a1.z = roundtf(a1.z); a1.w = roundtf(a1.w);
            *(float4*)(inputs + ((size_t)b * Nn + n) * (2 * Hh) + pass * Hh + q * 4) = a0;
            *(float4*)(inputs + ((size_t)b * Nn + n + 25) * (2 * Hh) + pass * Hh + q * 4) = a1;
        }
        __syncthreads();
    }
}

// ---------------- GRU gate math (float4 vectorized) --------------------------
__global__ void gru_kernel(const float4* __restrict__ gi,
                           const float4* __restrict__ cat,
                           const float4* __restrict__ h,
                           float4* __restrict__ newh, int total4) {
    int i = blockIdx.x * blockDim.x + threadIdx.x;
    if (i >= total4) return;
    int bn = i >> 5, qq = i & 31;
    size_t gibase = (size_t)bn * 96;
    size_t cbase  = (size_t)bn * 160;
    float4 ir = gi[gibase + qq];
    float4 ii = gi[gibase + 32 + qq];
    float4 in_ = gi[gibase + 64 + qq];
    float4 hr = cat[cbase + 64 + qq];
    float4 hi = cat[cbase + 96 + qq];
    float4 hn = cat[cbase + 128 + qq];
    float4 hv = h[i];
    float4 o;
#define GRU1(comp) { \
        float r = 1.f / (1.f + expf(-(ir.comp + hr.comp))); \
        float z = 1.f / (1.f + expf(-(ii.comp + hi.comp))); \
        float ng = tanhf(in_.comp + r * hn.comp); \
        o.comp = roundtf(ng + z * (hv.comp - ng)); }
    GRU1(x) GRU1(y) GRU1(z) GRU1(w)
#undef GRU1
    newh[i] = o;
}

// ---------------- ht only ----------------------------------------------------
__global__ void ht_kernel(const int* __restrict__ alias,
                          const int* __restrict__ mask,
                          const float* __restrict__ newh,
                          float* __restrict__ ht) {
    int b = blockIdx.x;
    int lane = threadIdx.x;                // 32 threads
    int c = 0;
    if (lane < Ss)      c += mask[b * Ss + lane];
    if (lane + 32 < Ss) c += mask[b * Ss + lane + 32];
#pragma unroll
    for (int off = 16; off; off >>= 1)
        c += __shfl_down_sync(0xffffffffu, c, off);
    c = __shfl_sync(0xffffffffu, c, 0);
    int node = alias[b * Ss + (c - 1)];
    const float4* hrow = (const float4*)newh + ((size_t)b * Nn + node) * (Hh / 4);
    ((float4*)ht)[(size_t)b * (Hh / 4) + lane] = hrow[lane];
}

// ---------------- attention readout ------------------------------------------
__global__ void attn_kernel(const float* __restrict__ q1,
                            const float* __restrict__ nq,
                            const float* __restrict__ fc3_w,
                            const float* __restrict__ newh,
                            const int* __restrict__ alias,
                            const int* __restrict__ mask,
                            float* __restrict__ avec) {
    int b = blockIdx.x;
    int tid = threadIdx.x;                 // 128
    int warp = tid >> 5, lane = tid & 31;
    __shared__ float salpha[Ss];
    __shared__ int sal[Ss];
    if (tid < Ss) sal[tid] = alias[b * Ss + tid];
    __syncthreads();
    for (int s = warp; s < Ss; s += 4) {
        size_t rowbase = ((size_t)b * Nn + sal[s]) * Hh;
        float part = 0.f;
        for (int hh = lane; hh < Hh; hh += 32) {
            float v = q1[(size_t)b * Hh + hh] + nq[rowbase + hh];
            part += fc3_w[hh] / (1.f + expf(-v));
        }
#pragma unroll
        for (int off = 16; off; off >>= 1)
            part += __shfl_down_sync(0xffffffffu, part, off);
        if (lane == 0) salpha[s] = part;
    }
    __syncthreads();
    int hh = tid;
    float acc = 0.f;
    for (int s = 0; s < Ss; s++) {
        float m = (float)mask[b * Ss + s];
        acc += salpha[s] * newh[((size_t)b * Nn + sal[s]) * Hh + hh] * m;
    }
    avec[(size_t)b * Hh + hh] = roundtf(acc);
}

// ---------------- launch -----------------------------------------------------
extern "C" void kernel_launch(void* const* d_in, const int* in_sizes, int n_in,
                              void* d_out, int out_size) {
    const int*   alias_inputs = (const int*)  d_in[0];
    const float* A            = (const float*)d_in[1];
    const int*   items        = (const int*)  d_in[2];
    const int*   mask         = (const int*)  d_in[3];
    const float* emb          = (const float*)d_in[4];
    const float* ein_w        = (const float*)d_in[5];
    const float* ein_b        = (const float*)d_in[6];
    const float* eou_w        = (const float*)d_in[7];
    const float* eou_b        = (const float*)d_in[8];
    const float* w_ih         = (const float*)d_in[9];
    const float* w_hh         = (const float*)d_in[10];
    const float* b_ih         = (const float*)d_in[11];
    const float* b_hh         = (const float*)d_in[12];
    const float* b_iah        = (const float*)d_in[13];
    const float* b_oah        = (const float*)d_in[14];
    const float* fc1_w        = (const float*)d_in[15];
    const float* fc1_b        = (const float*)d_in[16];
    const float* fc2_w        = (const float*)d_in[17];
    const float* fc2_b        = (const float*)d_in[18];
    const float* fc3_w        = (const float*)d_in[19];
    float* out = (float*)d_out;

    const int SM = 4 * TILEB;              // 90112 B (2-stage, A+B)
    cudaFuncSetAttribute(gemm2_kernel<false>,
                         cudaFuncAttributeMaxDynamicSharedMemorySize, SM);
    cudaFuncSetAttribute(gemm2_kernel<true>,
                         cudaFuncAttributeMaxDynamicSharedMemorySize, SM);

    float *p_h, *p_cat, *p_inputs, *p_gi, *p_newh;
    float *p_ht, *p_q1, *p_nq, *p_avec, *p_wr, *p_bcat;
    cudaGetSymbolAddress((void**)&p_h,      g_h);
    cudaGetSymbolAddress((void**)&p_cat,    g_cat);
    cudaGetSymbolAddress((void**)&p_inputs, g_inputs);
    cudaGetSymbolAddress((void**)&p_gi,     g_gi);
    cudaGetSymbolAddress((void**)&p_newh,   g_newh);
    cudaGetSymbolAddress((void**)&p_ht,     g_ht);
    cudaGetSymbolAddress((void**)&p_q1,     g_q1);
    cudaGetSymbolAddress((void**)&p_nq,     g_nq);
    cudaGetSymbolAddress((void**)&p_avec,   g_avec);
    cudaGetSymbolAddress((void**)&p_wr,     g_wr);
    cudaGetSymbolAddress((void**)&p_bcat,   g_bcat);

    const int BN = Bb * Nn;                // 51200 = 400 * 128

    // 0. prep
    pack_cat_kernel<<<(640 * 32 + 255) / 256, 256>>>(
        ein_w, eou_w, w_hh, ein_b, eou_b, b_hh, p_wr + WR_CAT, p_bcat);
    round_all_kernel<<<(32768 + 255) / 256, 256>>>(w_ih, fc1_w, fc2_w, p_wr);
    // 1. gather (rounds inline from raw emb)
    {
        int total4 = BN * (Hh / 4);
        gather_kernel<<<(total4 + 255) / 256, 256>>>(items, emb, p_h, total4);
    }
    // 2. cat GEMM: [hin|hout|gh] = h @ [ein;eou;whh]^T  (M=51200, N=640, K=128)
    gemm2_kernel<false><<<dim3(5, BN / 128), 256, SM>>>(p_h, p_wr + WR_CAT,
                                                        p_bcat, p_cat, BN, 640, Hh);
    // 3. adjacency matmuls
    amm_kernel<<<Bb, 256>>>(A, p_cat, b_iah, b_oah, p_inputs);
    // 4. gi  (N=384, K=256)
    gemm2_kernel<false><<<dim3(3, BN / 128), 256, SM>>>(p_inputs, p_wr + WR_WIH,
                                                        b_ih, p_gi, BN, 3 * Hh, 2 * Hh);
    // 5. GRU (float4)
    {
        int total4 = BN * (Hh / 4);
        gru_kernel<<<(total4 + 255) / 256, 256>>>((const float4*)p_gi,
                                                  (const float4*)p_cat,
                                                  (const float4*)p_h,
                                                  (float4*)p_newh, total4);
    }
    // 6. ht
    ht_kernel<<<Bb, 32>>>(alias_inputs, mask, p_newh, p_ht);
    // 7. q1 (M=1024, N=128, K=128)
    gemm2_kernel<false><<<dim3(1, Bb / 128), 256, SM>>>(p_ht, p_wr + WR_FC1,
                                                        fc1_b, p_q1, Bb, Hh, Hh);
    // 8. nq = newh @ fc2^T (+fc2_b)  (M=51200, N=128, K=128)
    gemm2_kernel<false><<<dim3(1, BN / 128), 256, SM>>>(p_newh, p_wr + WR_FC2,
                                                        fc2_b, p_nq, BN, Hh, Hh);
    // 9. attention
    attn_kernel<<<Bb, 128>>>(p_q1, p_nq, fc3_w, p_newh, alias_inputs, mask, p_avec);
    // 10. scoring: out = avec @ emb[1:].T  (raw emb, in-loop rna cvt on B)
    gemm2_kernel<true><<<dim3((V1 + 127) / 128, Bb / 128), 256, SM>>>(
        p_avec, emb + Hh, nullptr, out, Bb, V1, Hh);
    (void)in_sizes; (void)n_in; (void)out_size;
}